// round 3
// baseline (speedup 1.0000x reference)
#include <cuda_runtime.h>
#include <cuda_bf16.h>
#include <math.h>

#define B_   32
#define N_   196
#define E_   512
#define H_   8
#define HD_  64
#define L_   4
#define M_   (B_*N_)          // 6272 tokens
#define PD_  3840             // patch dim
#define NCLS_ 101
#define EPS_ 1e-5f

// ---------------- scratch (device globals; no cudaMalloc allowed) ------------
// x1 = g_x[0 : M*E), x2 = g_x[M*E : 2*M*E)  (contiguous so shared-weight ops batch)
__device__ float g_x[2*M_*E_];
__device__ float g_t[2*M_*E_];
__device__ float g_qkv[(size_t)2*M_*3*E_];
__device__ float g_q[M_*E_];
__device__ float g_kv[M_*2*E_];
__device__ float g_sc[(size_t)2*B_*H_*N_*N_];
__device__ float g_ao[2*M_*E_];
__device__ float g_hid[(size_t)2*M_*4*E_];
__device__ float g_patch[(size_t)M_*PD_];
__device__ float g_feat[B_*2*E_];
__device__ float g_clsh[B_*4*E_];

// ------- GEMM: C = act(A(M,K) @ W(N,K)^T + bias [+ res]), batched over z -----
#define BM 128
#define BN 128
#define BK 16

__global__ __launch_bounds__(256, 2)
void gemm_kernel(const float* __restrict__ A,
                 const float* __restrict__ W,
                 const float* __restrict__ bias,
                 const float* __restrict__ res,
                 float* __restrict__ C,
                 int M, int N, int K, int relu,
                 long sA, long sW, long sB, long sRes, long sC)
{
    int z = blockIdx.z;
    A += (size_t)z * sA;
    W += (size_t)z * sW;
    bias += (size_t)z * sB;
    if (res) res += (size_t)z * sRes;
    C += (size_t)z * sC;

    __shared__ float As[2][BK][BM+4];
    __shared__ float Ws[2][BK][BN+4];
    int tid = threadIdx.x;
    int tx = tid & 15, ty = tid >> 4;          // 16x16 thread grid, 8x8 microtile
    int m0 = blockIdx.y * BM, n0 = blockIdx.x * BN;

    float acc[8][8];
#pragma unroll
    for (int i = 0; i < 8; i++)
#pragma unroll
        for (int j = 0; j < 8; j++) acc[i][j] = 0.f;

    // staging registers for the next k-slab
    float4 aR[2], wR[2];
    // load mapping: 512 float4 per tile, 2 per thread.
    // row = tid>>2 + t*64 (0..127), kq = (tid&3)*4
    const int r0 = tid >> 2, kq0 = (tid & 3) << 2;

    // --- prologue: load slab 0 ---
#pragma unroll
    for (int t = 0; t < 2; t++) {
        int row = r0 + t * 64;
        int m = m0 + row;
        aR[t] = (m < M) ? *reinterpret_cast<const float4*>(A + (size_t)m*K + kq0)
                        : make_float4(0.f,0.f,0.f,0.f);
        int n = n0 + row;
        wR[t] = (n < N) ? *reinterpret_cast<const float4*>(W + (size_t)n*K + kq0)
                        : make_float4(0.f,0.f,0.f,0.f);
    }
    int p = 0;
#pragma unroll
    for (int t = 0; t < 2; t++) {
        int row = r0 + t * 64;
        As[p][kq0  ][row] = aR[t].x; As[p][kq0+1][row] = aR[t].y;
        As[p][kq0+2][row] = aR[t].z; As[p][kq0+3][row] = aR[t].w;
        Ws[p][kq0  ][row] = wR[t].x; Ws[p][kq0+1][row] = wR[t].y;
        Ws[p][kq0+2][row] = wR[t].z; Ws[p][kq0+3][row] = wR[t].w;
    }
    __syncthreads();

    for (int k0 = BK; k0 < K; k0 += BK) {
        // prefetch next slab to registers
#pragma unroll
        for (int t = 0; t < 2; t++) {
            int row = r0 + t * 64;
            int m = m0 + row;
            aR[t] = (m < M) ? *reinterpret_cast<const float4*>(A + (size_t)m*K + k0 + kq0)
                            : make_float4(0.f,0.f,0.f,0.f);
            int n = n0 + row;
            wR[t] = (n < N) ? *reinterpret_cast<const float4*>(W + (size_t)n*K + k0 + kq0)
                            : make_float4(0.f,0.f,0.f,0.f);
        }
        // compute current slab
#pragma unroll
        for (int kk = 0; kk < BK; kk++) {
            float a[8], b[8];
            *reinterpret_cast<float4*>(a)   = *reinterpret_cast<const float4*>(&As[p][kk][ty*8]);
            *reinterpret_cast<float4*>(a+4) = *reinterpret_cast<const float4*>(&As[p][kk][ty*8+4]);
            *reinterpret_cast<float4*>(b)   = *reinterpret_cast<const float4*>(&Ws[p][kk][tx*8]);
            *reinterpret_cast<float4*>(b+4) = *reinterpret_cast<const float4*>(&Ws[p][kk][tx*8+4]);
#pragma unroll
            for (int i = 0; i < 8; i++)
#pragma unroll
                for (int j = 0; j < 8; j++)
                    acc[i][j] += a[i]*b[j];
        }
        // store next slab to the other buffer
        int q = p ^ 1;
#pragma unroll
        for (int t = 0; t < 2; t++) {
            int row = r0 + t * 64;
            As[q][kq0  ][row] = aR[t].x; As[q][kq0+1][row] = aR[t].y;
            As[q][kq0+2][row] = aR[t].z; As[q][kq0+3][row] = aR[t].w;
            Ws[q][kq0  ][row] = wR[t].x; Ws[q][kq0+1][row] = wR[t].y;
            Ws[q][kq0+2][row] = wR[t].z; Ws[q][kq0+3][row] = wR[t].w;
        }
        __syncthreads();
        p = q;
    }
    // last slab
#pragma unroll
    for (int kk = 0; kk < BK; kk++) {
        float a[8], b[8];
        *reinterpret_cast<float4*>(a)   = *reinterpret_cast<const float4*>(&As[p][kk][ty*8]);
        *reinterpret_cast<float4*>(a+4) = *reinterpret_cast<const float4*>(&As[p][kk][ty*8+4]);
        *reinterpret_cast<float4*>(b)   = *reinterpret_cast<const float4*>(&Ws[p][kk][tx*8]);
        *reinterpret_cast<float4*>(b+4) = *reinterpret_cast<const float4*>(&Ws[p][kk][tx*8+4]);
#pragma unroll
        for (int i = 0; i < 8; i++)
#pragma unroll
            for (int j = 0; j < 8; j++)
                acc[i][j] += a[i]*b[j];
    }

    // epilogue
#pragma unroll
    for (int i = 0; i < 8; i++) {
        int m = m0 + ty*8 + i;
        if (m >= M) continue;
#pragma unroll
        for (int j = 0; j < 8; j++) {
            int n = n0 + tx*8 + j;
            if (n >= N) continue;
            float v = acc[i][j] + bias[n];
            if (res) v += res[(size_t)m*N + n];
            if (relu) v = fmaxf(v, 0.f);
            C[(size_t)m*N + n] = v;
        }
    }
}

// ---------------- LayerNorm over 512 ----------------------------------------
__global__ void ln_kernel(const float* __restrict__ x,
                          const float* __restrict__ g,
                          const float* __restrict__ b,
                          float* __restrict__ y)
{
    int row = blockIdx.x;
    const float* xr = x + (size_t)row * E_;
    int tid = threadIdx.x;
    float v0 = xr[tid], v1 = xr[tid + 256];
    float s  = v0 + v1;
    float ss = v0*v0 + v1*v1;
#pragma unroll
    for (int o = 16; o > 0; o >>= 1) {
        s  += __shfl_xor_sync(0xffffffffu, s,  o);
        ss += __shfl_xor_sync(0xffffffffu, ss, o);
    }
    __shared__ float sh[16];
    int w = tid >> 5, lane = tid & 31;
    if (lane == 0) { sh[w] = s; sh[8+w] = ss; }
    __syncthreads();
    if (tid == 0) {
        float a = 0.f, c = 0.f;
        for (int i = 0; i < 8; i++) { a += sh[i]; c += sh[8+i]; }
        sh[0] = a; sh[8] = c;
    }
    __syncthreads();
    float mean = sh[0] * (1.f/E_);
    float var  = sh[8] * (1.f/E_) - mean*mean;
    float rs = rsqrtf(var + EPS_);
    float* yr = y + (size_t)row * E_;
    yr[tid]       = (v0 - mean) * rs * g[tid]       + b[tid];
    yr[tid + 256] = (v1 - mean) * rs * g[tid + 256] + b[tid + 256];
}

// ---------------- shifted-patch gather + LN(3840) ----------------------------
__global__ void patch_ln_kernel(const float* __restrict__ image,
                                const float* __restrict__ g,
                                const float* __restrict__ bb)
{
    __shared__ float buf[PD_];
    __shared__ float sh[16];
    int bn = blockIdx.x;
    int b  = bn / N_, n = bn % N_;
    int ph = n / 14, pw = n % 14;
    int tid = threadIdx.x;

    float s = 0.f, ss = 0.f;
    for (int d = tid; d < PD_; d += 256) {
        int c  = d % 15, t = d / 15;
        int p2 = t % 16, p1 = t / 16;
        int sh_idx = c / 3, ch = c % 3;
        int row = ph*16 + p1, col = pw*16 + p2;
        if      (sh_idx == 1) col -= 1;
        else if (sh_idx == 2) col += 1;
        else if (sh_idx == 3) row -= 1;
        else if (sh_idx == 4) row += 1;
        float v = 0.f;
        if (row >= 0 && row < 224 && col >= 0 && col < 224)
            v = image[(((size_t)b*3 + ch)*224 + row)*224 + col];
        buf[d] = v;
        s += v; ss += v*v;
    }
#pragma unroll
    for (int o = 16; o > 0; o >>= 1) {
        s  += __shfl_xor_sync(0xffffffffu, s,  o);
        ss += __shfl_xor_sync(0xffffffffu, ss, o);
    }
    int w = tid >> 5, lane = tid & 31;
    if (lane == 0) { sh[w] = s; sh[8+w] = ss; }
    __syncthreads();
    if (tid == 0) {
        float a = 0.f, c = 0.f;
        for (int i = 0; i < 8; i++) { a += sh[i]; c += sh[8+i]; }
        sh[0] = a; sh[8] = c;
    }
    __syncthreads();
    float mean = sh[0] * (1.f/PD_);
    float var  = sh[8] * (1.f/PD_) - mean*mean;
    float rs = rsqrtf(var + EPS_);
    float* out = g_patch + (size_t)bn * PD_;
    for (int d = tid; d < PD_; d += 256)
        out[d] = (buf[d] - mean) * rs * g[d] + bb[d];
}

// ---------------- positional add (buggy batch-indexed sinusoid, per ref) -----
__global__ void posadd_kernel()
{
    int idx = blockIdx.x * 256 + threadIdx.x;
    if (idx >= 2*M_*E_) return;
    int e = idx & (E_-1);
    int stream_rem = idx % (M_*E_);
    int b = stream_rem / (N_*E_);
    float p = (float)(b + 1);
    int i = e & 255;
    float f = expf(-(float)i * (9.210340371976184f / 255.0f));
    float ang = p * f;
    float v = (e < 256) ? sinf(ang) : cosf(ang);
    g_x[idx] += v;
}

// ---------------- attention: scores = scale * Q K^T  (batched over z) --------
__global__ void scores_kernel(const float* __restrict__ Qp,
                              const float* __restrict__ Kp,
                              int qstride, int kstride,
                              long qz, long kz, float scale)
{
    int zz = blockIdx.z;                 // [0, nz*256)
    int z  = zz >> 8;                    // B*H = 256
    int bh = zz & 255;
    int b = bh >> 3, h = bh & 7;
    Qp += (size_t)z * qz;
    Kp += (size_t)z * kz;
    float* sc = g_sc + (size_t)zz * N_ * N_;
    int q0 = blockIdx.y * 16, k0 = blockIdx.x * 16;
    __shared__ float qs[16][68];
    __shared__ float ks[16][68];
    int tid = threadIdx.x;
    int r = tid >> 4, c4 = (tid & 15) * 4;
    {
        int q = q0 + r;
        float4 v = make_float4(0.f,0.f,0.f,0.f);
        if (q < N_) v = *reinterpret_cast<const float4*>(Qp + (size_t)(b*N_+q)*qstride + h*HD_ + c4);
        qs[r][c4]=v.x; qs[r][c4+1]=v.y; qs[r][c4+2]=v.z; qs[r][c4+3]=v.w;
        int k = k0 + r;
        float4 w = make_float4(0.f,0.f,0.f,0.f);
        if (k < N_) w = *reinterpret_cast<const float4*>(Kp + (size_t)(b*N_+k)*kstride + h*HD_ + c4);
        ks[r][c4]=w.x; ks[r][c4+1]=w.y; ks[r][c4+2]=w.z; ks[r][c4+3]=w.w;
    }
    __syncthreads();
    int ty = tid >> 4, tx = tid & 15;
    float s = 0.f;
#pragma unroll
    for (int d = 0; d < HD_; d++) s += qs[ty][d] * ks[tx][d];
    int q = q0 + ty, k = k0 + tx;
    if (q < N_ && k < N_)
        sc[(size_t)q*N_ + k] = s * scale;
}

// ---------------- row softmax over 196 ---------------------------------------
__global__ void softmax_kernel(int nrows)
{
    int gw = (blockIdx.x * blockDim.x + threadIdx.x) >> 5;
    if (gw >= nrows) return;
    int lane = threadIdx.x & 31;
    float* row = g_sc + (size_t)gw * N_;
    float vals[7];
    float mx = -1e30f;
#pragma unroll
    for (int i = 0; i < 7; i++) {
        int j = lane + 32*i;
        vals[i] = (j < N_) ? row[j] : -1e30f;
        mx = fmaxf(mx, vals[i]);
    }
#pragma unroll
    for (int o = 16; o > 0; o >>= 1) mx = fmaxf(mx, __shfl_xor_sync(0xffffffffu, mx, o));
    float sum = 0.f;
#pragma unroll
    for (int i = 0; i < 7; i++) { vals[i] = expf(vals[i] - mx); sum += vals[i]; }
#pragma unroll
    for (int o = 16; o > 0; o >>= 1) sum += __shfl_xor_sync(0xffffffffu, sum, o);
    float inv = 1.f / sum;
#pragma unroll
    for (int i = 0; i < 7; i++) {
        int j = lane + 32*i;
        if (j < N_) row[j] = vals[i] * inv;
    }
}

// ---------------- PV (batched over z) ----------------------------------------
__global__ void pv_kernel(const float* __restrict__ Vp, int vstride,
                          long vz, long oz, float* __restrict__ Out)
{
    int zz = blockIdx.y;
    int z  = zz >> 8;
    int bh = zz & 255;
    int b = bh >> 3, h = bh & 7;
    Vp  += (size_t)z * vz;
    Out += (size_t)z * oz;
    const float* P = g_sc + (size_t)zz * N_ * N_;
    int q0 = blockIdx.x * 32;
    __shared__ float Ps[32][17];
    __shared__ float Vs[16][64];
    int tid = threadIdx.x;
    int tx = tid & 63, ty = tid >> 6;
    float acc[8];
#pragma unroll
    for (int i = 0; i < 8; i++) acc[i] = 0.f;

    for (int k0 = 0; k0 < N_; k0 += 16) {
        {
            int pr = tid >> 3, pc = (tid & 7) * 2;
#pragma unroll
            for (int j = 0; j < 2; j++) {
                int q = q0 + pr, k = k0 + pc + j;
                Ps[pr][pc+j] = (q < N_ && k < N_) ? P[(size_t)q*N_ + k] : 0.f;
            }
        }
        {
            int vr = tid >> 4, vc = (tid & 15) * 4;
            int k = k0 + vr;
            float4 v = make_float4(0.f,0.f,0.f,0.f);
            if (k < N_) v = *reinterpret_cast<const float4*>(Vp + (size_t)(b*N_+k)*vstride + h*HD_ + vc);
            Vs[vr][vc]=v.x; Vs[vr][vc+1]=v.y; Vs[vr][vc+2]=v.z; Vs[vr][vc+3]=v.w;
        }
        __syncthreads();
#pragma unroll
        for (int kk = 0; kk < 16; kk++) {
            float vv = Vs[kk][tx];
#pragma unroll
            for (int i = 0; i < 8; i++)
                acc[i] += Ps[ty + 4*i][kk] * vv;
        }
        __syncthreads();
    }
#pragma unroll
    for (int i = 0; i < 8; i++) {
        int q = q0 + ty + 4*i;
        if (q < N_)
            Out[(size_t)(b*N_+q)*E_ + h*HD_ + tx] = acc[i];
    }
}

// ---------------- final LN of last token -> feat (B, 2E) ---------------------
__global__ void final_feat_kernel(const float* __restrict__ g,
                                  const float* __restrict__ b)
{
    int s = blockIdx.x >> 5;   // stream 0/1
    int bb = blockIdx.x & 31;  // batch
    const float* src = g_x + ((size_t)s*M_ + bb*N_ + (N_-1)) * E_;
    int tid = threadIdx.x;
    float v0 = src[tid], v1 = src[tid + 256];
    float ssum = v0 + v1, sq = v0*v0 + v1*v1;
#pragma unroll
    for (int o = 16; o > 0; o >>= 1) {
        ssum += __shfl_xor_sync(0xffffffffu, ssum, o);
        sq   += __shfl_xor_sync(0xffffffffu, sq,   o);
    }
    __shared__ float sh[16];
    int w = tid >> 5, lane = tid & 31;
    if (lane == 0) { sh[w] = ssum; sh[8+w] = sq; }
    __syncthreads();
    if (tid == 0) {
        float a = 0.f, c = 0.f;
        for (int i = 0; i < 8; i++) { a += sh[i]; c += sh[8+i]; }
        sh[0] = a; sh[8] = c;
    }
    __syncthreads();
    float mean = sh[0] * (1.f/E_);
    float var  = sh[8] * (1.f/E_) - mean*mean;
    float rs = rsqrtf(var + EPS_);
    float* dst = g_feat + (size_t)bb * (2*E_) + s*E_;
    dst[tid]       = (v0 - mean) * rs * g[tid]       + b[tid];
    dst[tid + 256] = (v1 - mean) * rs * g[tid + 256] + b[tid + 256];
}

// ---------------- host-side orchestration ------------------------------------
static inline void gemmB(const float* A, const float* W, const float* bias,
                         const float* res, float* C, int M, int N, int K,
                         int relu, int nz,
                         long sA, long sW, long sB, long sRes, long sC)
{
    dim3 grid((N + BN - 1)/BN, (M + BM - 1)/BM, nz);
    gemm_kernel<<<grid, 256>>>(A, W, bias, res, C, M, N, K, relu,
                               sA, sW, sB, sRes, sC);
}

extern "C" void kernel_launch(void* const* d_in, const int* in_sizes, int n_in,
                              void* d_out, int out_size)
{
    const float* image      = (const float*)d_in[0];
    const float* text_hidden= (const float*)d_in[1];
    const float* patch_ln_g = (const float*)d_in[2];
    const float* patch_ln_b = (const float*)d_in[3];
    const float* patch_w    = (const float*)d_in[4];
    const float* patch_b    = (const float*)d_in[5];
    const float* text_w     = (const float*)d_in[6];
    const float* text_b     = (const float*)d_in[7];
    const float* attn_in_w  = (const float*)d_in[8];
    const float* attn_in_b  = (const float*)d_in[9];
    const float* attn_out_w = (const float*)d_in[10];
    const float* attn_out_b = (const float*)d_in[11];
    const float* mlp_w1     = (const float*)d_in[12];
    const float* mlp_b1     = (const float*)d_in[13];
    const float* mlp_w2     = (const float*)d_in[14];
    const float* mlp_b2     = (const float*)d_in[15];
    const float* ln_gamma   = (const float*)d_in[16];
    const float* ln_beta    = (const float*)d_in[17];
    const float* fin_g      = (const float*)d_in[18];
    const float* fin_b      = (const float*)d_in[19];
    const float* cls_w1     = (const float*)d_in[20];
    const float* cls_b1     = (const float*)d_in[21];
    const float* cls_w2     = (const float*)d_in[22];
    const float* cls_b2     = (const float*)d_in[23];

    float *xp,*tp,*qkvp,*qp,*kvp,*aop,*hidp,*patchp,*featp,*clshp;
    cudaGetSymbolAddress((void**)&xp,    g_x);
    cudaGetSymbolAddress((void**)&tp,    g_t);
    cudaGetSymbolAddress((void**)&qkvp,  g_qkv);
    cudaGetSymbolAddress((void**)&qp,    g_q);
    cudaGetSymbolAddress((void**)&kvp,   g_kv);
    cudaGetSymbolAddress((void**)&aop,   g_ao);
    cudaGetSymbolAddress((void**)&hidp,  g_hid);
    cudaGetSymbolAddress((void**)&patchp,g_patch);
    cudaGetSymbolAddress((void**)&featp, g_feat);
    cudaGetSymbolAddress((void**)&clshp, g_clsh);

    float* x1p = xp;
    float* x2p = xp + (size_t)M_*E_;

    const float scale = 0.125f;  // 1/sqrt(64)
    dim3 sc_grid2(13, 13, 2*B_*H_);
    dim3 sc_grid1(13, 13, B_*H_);
    dim3 pv_grid2(7, 2*B_*H_);
    dim3 pv_grid1(7, B_*H_);
    int sm2 = (2*B_*H_*N_*32 + 127) / 128;
    int sm1 = (B_*H_*N_*32 + 127) / 128;

    // --- embedding ---
    patch_ln_kernel<<<M_, 256>>>(image, patch_ln_g, patch_ln_b);
    gemmB(patchp, patch_w, patch_b, nullptr, x1p, M_, E_, PD_, 0, 1, 0,0,0,0,0);
    gemmB(text_hidden, text_w, text_b, nullptr, x2p, M_, E_, 768, 0, 1, 0,0,0,0,0);
    posadd_kernel<<<(2*M_*E_ + 255)/256, 256>>>();

    for (int l = 0; l < L_; l++) {
        const float* g0 = ln_gamma + (size_t)(l*2+0)*E_;
        const float* b0 = ln_beta  + (size_t)(l*2+0)*E_;
        const float* g1 = ln_gamma + (size_t)(l*2+1)*E_;
        const float* b1 = ln_beta  + (size_t)(l*2+1)*E_;

        // --- self-attention, both streams batched (z = stream) ---
        {
            const float* wi = attn_in_w  + (size_t)(l*3)*1536*E_;
            const float* bi = attn_in_b  + (size_t)(l*3)*1536;
            const float* wo = attn_out_w + (size_t)(l*3)*E_*E_;
            const float* bo = attn_out_b + (size_t)(l*3)*E_;
            ln_kernel<<<2*M_, 256>>>(xp, g0, b0, tp);
            gemmB(tp, wi, bi, nullptr, qkvp, M_, 1536, E_, 0, 2,
                  (long)M_*E_, (long)1536*E_, 1536, 0, (long)M_*1536);
            scores_kernel<<<sc_grid2, 256>>>(qkvp, qkvp + E_, 1536, 1536,
                                             (long)M_*1536, (long)M_*1536, scale);
            softmax_kernel<<<sm2, 128>>>(2*B_*H_*N_);
            pv_kernel<<<pv_grid2, 256>>>(qkvp + 2*E_, 1536,
                                         (long)M_*1536, (long)M_*E_, aop);
            gemmB(aop, wo, bo, xp, xp, M_, E_, E_, 0, 2,
                  (long)M_*E_, (long)E_*E_, E_, (long)M_*E_, (long)M_*E_);
        }

        // --- guide attention: q from x2, kv from x1, overwrites x1 ---
        {
            const float* wi = attn_in_w  + (size_t)(l*3+2)*1536*E_;
            const float* bi = attn_in_b  + (size_t)(l*3+2)*1536;
            const float* wo = attn_out_w + (size_t)(l*3+2)*E_*E_;
            const float* bo = attn_out_b + (size_t)(l*3+2)*E_;
            gemmB(x2p, wi, bi, nullptr, qp, M_, E_, E_, 0, 1, 0,0,0,0,0);
            gemmB(x1p, wi + (size_t)E_*E_, bi + E_, nullptr, kvp, M_, 2*E_, E_, 0, 1, 0,0,0,0,0);
            scores_kernel<<<sc_grid1, 256>>>(qp, kvp, E_, 2*E_, 0, 0, scale);
            softmax_kernel<<<sm1, 128>>>(B_*H_*N_);
            pv_kernel<<<pv_grid1, 256>>>(kvp + E_, 2*E_, 0, 0, aop);
            gemmB(aop, wo, bo, nullptr, x1p, M_, E_, E_, 0, 1, 0,0,0,0,0);
        }

        // --- MLP, both streams in one M=12544 GEMM (shared weights) ---
        {
            const float* w1  = mlp_w1 + (size_t)l*4*E_*E_;
            const float* bb1 = mlp_b1 + (size_t)l*4*E_;
            const float* w2  = mlp_w2 + (size_t)l*E_*4*E_;
            const float* bb2 = mlp_b2 + (size_t)l*E_;
            ln_kernel<<<2*M_, 256>>>(xp, g1, b1, tp);
            gemmB(tp, w1, bb1, nullptr, hidp, 2*M_, 4*E_, E_, 1, 1, 0,0,0,0,0);
            gemmB(hidp, w2, bb2, xp, xp, 2*M_, E_, 4*E_, 0, 1, 0,0,0,0,0);
        }
    }

    // --- head ---
    final_feat_kernel<<<64, 256>>>(fin_g, fin_b);
    gemmB(featp, cls_w1, cls_b1, nullptr, clshp, B_, 4*E_, 2*E_, 1, 1, 0,0,0,0,0);
    gemmB(clshp, cls_w2, cls_b2, nullptr, (float*)d_out, B_, NCLS_, 4*E_, 0, 1, 0,0,0,0,0);
}

// round 4
// speedup vs baseline: 1.0252x; 1.0252x over previous
#include <cuda_runtime.h>
#include <cuda_bf16.h>
#include <math.h>

#define B_   32
#define N_   196
#define E_   512
#define H_   8
#define HD_  64
#define L_   4
#define M_   (B_*N_)          // 6272 tokens
#define PD_  3840             // patch dim
#define NCLS_ 101
#define EPS_ 1e-5f

// ---------------- scratch (device globals; no cudaMalloc allowed) ------------
__device__ float g_x[2*M_*E_];
__device__ float g_t[2*M_*E_];
__device__ float g_qkv[(size_t)2*M_*3*E_];
__device__ float g_q[M_*E_];
__device__ float g_kv[M_*2*E_];
__device__ float g_sc[(size_t)2*B_*H_*N_*N_];
__device__ float g_ao[2*M_*E_];
__device__ float g_hid[(size_t)2*M_*4*E_];
__device__ float g_patch[(size_t)M_*PD_];
__device__ float g_feat[B_*2*E_];
__device__ float g_clsh[B_*4*E_];

// ---- packed fp32x2 helpers (sm_100+; exact fp32 math, 2x FMA issue rate) ----
__device__ __forceinline__ unsigned long long pk2(float lo, float hi) {
    unsigned long long r;
    asm("mov.b64 %0, {%1, %2};" : "=l"(r) : "f"(lo), "f"(hi));
    return r;
}
__device__ __forceinline__ void upk2(float& lo, float& hi, unsigned long long v) {
    asm("mov.b64 {%0, %1}, %2;" : "=f"(lo), "=f"(hi) : "l"(v));
}
__device__ __forceinline__ void ffma2(unsigned long long& acc,
                                      unsigned long long a,
                                      unsigned long long b) {
    asm("fma.rn.f32x2 %0, %1, %2, %0;" : "+l"(acc) : "l"(a), "l"(b));
}

// ------- GEMM: C = act(A(M,K) @ W(N,K)^T + bias [+ res]), batched over z -----
#define BM 128
#define BN 128
#define BK 16

__global__ __launch_bounds__(256, 2)
void gemm_kernel(const float* __restrict__ A,
                 const float* __restrict__ W,
                 const float* __restrict__ bias,
                 const float* __restrict__ res,
                 float* __restrict__ C,
                 int M, int N, int K, int relu,
                 long sA, long sW, long sB, long sRes, long sC)
{
    int z = blockIdx.z;
    A += (size_t)z * sA;
    W += (size_t)z * sW;
    bias += (size_t)z * sB;
    if (res) res += (size_t)z * sRes;
    C += (size_t)z * sC;

    __shared__ float As[2][BK][BM+4];
    __shared__ float Ws[2][BK][BN+4];
    int tid = threadIdx.x;
    int tx = tid & 15, ty = tid >> 4;          // 16x16 thread grid, 8x8 microtile
    int m0 = blockIdx.y * BM, n0 = blockIdx.x * BN;

    // 8x8 fp32 accumulator as 8x4 packed f32x2 (n-pairs)
    unsigned long long acc2[8][4];
    const unsigned long long z2 = pk2(0.f, 0.f);
#pragma unroll
    for (int i = 0; i < 8; i++)
#pragma unroll
        for (int j = 0; j < 4; j++) acc2[i][j] = z2;

    float4 aR[2], wR[2];
    const int r0 = tid >> 2, kq0 = (tid & 3) << 2;

    // --- prologue: load slab 0 ---
#pragma unroll
    for (int t = 0; t < 2; t++) {
        int row = r0 + t * 64;
        int m = m0 + row;
        aR[t] = (m < M) ? *reinterpret_cast<const float4*>(A + (size_t)m*K + kq0)
                        : make_float4(0.f,0.f,0.f,0.f);
        int n = n0 + row;
        wR[t] = (n < N) ? *reinterpret_cast<const float4*>(W + (size_t)n*K + kq0)
                        : make_float4(0.f,0.f,0.f,0.f);
    }
    int p = 0;
#pragma unroll
    for (int t = 0; t < 2; t++) {
        int row = r0 + t * 64;
        As[p][kq0  ][row] = aR[t].x; As[p][kq0+1][row] = aR[t].y;
        As[p][kq0+2][row] = aR[t].z; As[p][kq0+3][row] = aR[t].w;
        Ws[p][kq0  ][row] = wR[t].x; Ws[p][kq0+1][row] = wR[t].y;
        Ws[p][kq0+2][row] = wR[t].z; Ws[p][kq0+3][row] = wR[t].w;
    }
    __syncthreads();

    for (int k0 = BK; k0 < K; k0 += BK) {
        // prefetch next slab to registers
#pragma unroll
        for (int t = 0; t < 2; t++) {
            int row = r0 + t * 64;
            int m = m0 + row;
            aR[t] = (m < M) ? *reinterpret_cast<const float4*>(A + (size_t)m*K + k0 + kq0)
                            : make_float4(0.f,0.f,0.f,0.f);
            int n = n0 + row;
            wR[t] = (n < N) ? *reinterpret_cast<const float4*>(W + (size_t)n*K + k0 + kq0)
                            : make_float4(0.f,0.f,0.f,0.f);
        }
        // compute current slab (packed f32x2)
#pragma unroll
        for (int kk = 0; kk < BK; kk++) {
            float a[8], b[8];
            *reinterpret_cast<float4*>(a)   = *reinterpret_cast<const float4*>(&As[p][kk][ty*8]);
            *reinterpret_cast<float4*>(a+4) = *reinterpret_cast<const float4*>(&As[p][kk][ty*8+4]);
            *reinterpret_cast<float4*>(b)   = *reinterpret_cast<const float4*>(&Ws[p][kk][tx*8]);
            *reinterpret_cast<float4*>(b+4) = *reinterpret_cast<const float4*>(&Ws[p][kk][tx*8+4]);
            unsigned long long bp[4];
#pragma unroll
            for (int j = 0; j < 4; j++) bp[j] = pk2(b[2*j], b[2*j+1]);
#pragma unroll
            for (int i = 0; i < 8; i++) {
                unsigned long long ap = pk2(a[i], a[i]);
#pragma unroll
                for (int j = 0; j < 4; j++)
                    ffma2(acc2[i][j], ap, bp[j]);
            }
        }
        // store next slab to the other buffer
        int q = p ^ 1;
#pragma unroll
        for (int t = 0; t < 2; t++) {
            int row = r0 + t * 64;
            As[q][kq0  ][row] = aR[t].x; As[q][kq0+1][row] = aR[t].y;
            As[q][kq0+2][row] = aR[t].z; As[q][kq0+3][row] = aR[t].w;
            Ws[q][kq0  ][row] = wR[t].x; Ws[q][kq0+1][row] = wR[t].y;
            Ws[q][kq0+2][row] = wR[t].z; Ws[q][kq0+3][row] = wR[t].w;
        }
        __syncthreads();
        p = q;
    }
    // last slab
#pragma unroll
    for (int kk = 0; kk < BK; kk++) {
        float a[8], b[8];
        *reinterpret_cast<float4*>(a)   = *reinterpret_cast<const float4*>(&As[p][kk][ty*8]);
        *reinterpret_cast<float4*>(a+4) = *reinterpret_cast<const float4*>(&As[p][kk][ty*8+4]);
        *reinterpret_cast<float4*>(b)   = *reinterpret_cast<const float4*>(&Ws[p][kk][tx*8]);
        *reinterpret_cast<float4*>(b+4) = *reinterpret_cast<const float4*>(&Ws[p][kk][tx*8+4]);
        unsigned long long bp[4];
#pragma unroll
        for (int j = 0; j < 4; j++) bp[j] = pk2(b[2*j], b[2*j+1]);
#pragma unroll
        for (int i = 0; i < 8; i++) {
            unsigned long long ap = pk2(a[i], a[i]);
#pragma unroll
            for (int j = 0; j < 4; j++)
                ffma2(acc2[i][j], ap, bp[j]);
        }
    }

    // epilogue
#pragma unroll
    for (int i = 0; i < 8; i++) {
        int m = m0 + ty*8 + i;
        if (m >= M) continue;
#pragma unroll
        for (int j = 0; j < 4; j++) {
            float v0, v1;
            upk2(v0, v1, acc2[i][j]);
            int n = n0 + tx*8 + 2*j;
            if (n < N) {
                float v = v0 + bias[n];
                if (res) v += res[(size_t)m*N + n];
                if (relu) v = fmaxf(v, 0.f);
                C[(size_t)m*N + n] = v;
            }
            if (n + 1 < N) {
                float v = v1 + bias[n+1];
                if (res) v += res[(size_t)m*N + n + 1];
                if (relu) v = fmaxf(v, 0.f);
                C[(size_t)m*N + n + 1] = v;
            }
        }
    }
}

// ---------------- LayerNorm over 512 ----------------------------------------
__global__ void ln_kernel(const float* __restrict__ x,
                          const float* __restrict__ g,
                          const float* __restrict__ b,
                          float* __restrict__ y)
{
    int row = blockIdx.x;
    const float* xr = x + (size_t)row * E_;
    int tid = threadIdx.x;
    float v0 = xr[tid], v1 = xr[tid + 256];
    float s  = v0 + v1;
    float ss = v0*v0 + v1*v1;
#pragma unroll
    for (int o = 16; o > 0; o >>= 1) {
        s  += __shfl_xor_sync(0xffffffffu, s,  o);
        ss += __shfl_xor_sync(0xffffffffu, ss, o);
    }
    __shared__ float sh[16];
    int w = tid >> 5, lane = tid & 31;
    if (lane == 0) { sh[w] = s; sh[8+w] = ss; }
    __syncthreads();
    if (tid == 0) {
        float a = 0.f, c = 0.f;
        for (int i = 0; i < 8; i++) { a += sh[i]; c += sh[8+i]; }
        sh[0] = a; sh[8] = c;
    }
    __syncthreads();
    float mean = sh[0] * (1.f/E_);
    float var  = sh[8] * (1.f/E_) - mean*mean;
    float rs = rsqrtf(var + EPS_);
    float* yr = y + (size_t)row * E_;
    yr[tid]       = (v0 - mean) * rs * g[tid]       + b[tid];
    yr[tid + 256] = (v1 - mean) * rs * g[tid + 256] + b[tid + 256];
}

// ---------------- shifted-patch gather + LN(3840) ----------------------------
__global__ void patch_ln_kernel(const float* __restrict__ image,
                                const float* __restrict__ g,
                                const float* __restrict__ bb)
{
    __shared__ float buf[PD_];
    __shared__ float sh[16];
    int bn = blockIdx.x;
    int b  = bn / N_, n = bn % N_;
    int ph = n / 14, pw = n % 14;
    int tid = threadIdx.x;

    float s = 0.f, ss = 0.f;
    for (int d = tid; d < PD_; d += 256) {
        int c  = d % 15, t = d / 15;
        int p2 = t % 16, p1 = t / 16;
        int sh_idx = c / 3, ch = c % 3;
        int row = ph*16 + p1, col = pw*16 + p2;
        if      (sh_idx == 1) col -= 1;
        else if (sh_idx == 2) col += 1;
        else if (sh_idx == 3) row -= 1;
        else if (sh_idx == 4) row += 1;
        float v = 0.f;
        if (row >= 0 && row < 224 && col >= 0 && col < 224)
            v = image[(((size_t)b*3 + ch)*224 + row)*224 + col];
        buf[d] = v;
        s += v; ss += v*v;
    }
#pragma unroll
    for (int o = 16; o > 0; o >>= 1) {
        s  += __shfl_xor_sync(0xffffffffu, s,  o);
        ss += __shfl_xor_sync(0xffffffffu, ss, o);
    }
    int w = tid >> 5, lane = tid & 31;
    if (lane == 0) { sh[w] = s; sh[8+w] = ss; }
    __syncthreads();
    if (tid == 0) {
        float a = 0.f, c = 0.f;
        for (int i = 0; i < 8; i++) { a += sh[i]; c += sh[8+i]; }
        sh[0] = a; sh[8] = c;
    }
    __syncthreads();
    float mean = sh[0] * (1.f/PD_);
    float var  = sh[8] * (1.f/PD_) - mean*mean;
    float rs = rsqrtf(var + EPS_);
    float* out = g_patch + (size_t)bn * PD_;
    for (int d = tid; d < PD_; d += 256)
        out[d] = (buf[d] - mean) * rs * g[d] + bb[d];
}

// ---------------- positional add (buggy batch-indexed sinusoid, per ref) -----
__global__ void posadd_kernel()
{
    int idx = blockIdx.x * 256 + threadIdx.x;
    if (idx >= 2*M_*E_) return;
    int e = idx & (E_-1);
    int stream_rem = idx % (M_*E_);
    int b = stream_rem / (N_*E_);
    float p = (float)(b + 1);
    int i = e & 255;
    float f = expf(-(float)i * (9.210340371976184f / 255.0f));
    float ang = p * f;
    float v = (e < 256) ? sinf(ang) : cosf(ang);
    g_x[idx] += v;
}

// ---------------- attention: scores = scale * Q K^T  (batched over z) --------
__global__ void scores_kernel(const float* __restrict__ Qp,
                              const float* __restrict__ Kp,
                              int qstride, int kstride,
                              long qz, long kz, float scale)
{
    int zz = blockIdx.z;                 // [0, nz*256)
    int z  = zz >> 8;                    // B*H = 256
    int bh = zz & 255;
    int b = bh >> 3, h = bh & 7;
    Qp += (size_t)z * qz;
    Kp += (size_t)z * kz;
    float* sc = g_sc + (size_t)zz * N_ * N_;
    int q0 = blockIdx.y * 16, k0 = blockIdx.x * 16;
    __shared__ float qs[16][68];
    __shared__ float ks[16][68];
    int tid = threadIdx.x;
    int r = tid >> 4, c4 = (tid & 15) * 4;
    {
        int q = q0 + r;
        float4 v = make_float4(0.f,0.f,0.f,0.f);
        if (q < N_) v = *reinterpret_cast<const float4*>(Qp + (size_t)(b*N_+q)*qstride + h*HD_ + c4);
        qs[r][c4]=v.x; qs[r][c4+1]=v.y; qs[r][c4+2]=v.z; qs[r][c4+3]=v.w;
        int k = k0 + r;
        float4 w = make_float4(0.f,0.f,0.f,0.f);
        if (k < N_) w = *reinterpret_cast<const float4*>(Kp + (size_t)(b*N_+k)*kstride + h*HD_ + c4);
        ks[r][c4]=w.x; ks[r][c4+1]=w.y; ks[r][c4+2]=w.z; ks[r][c4+3]=w.w;
    }
    __syncthreads();
    int ty = tid >> 4, tx = tid & 15;
    float s = 0.f;
#pragma unroll
    for (int d = 0; d < HD_; d++) s += qs[ty][d] * ks[tx][d];
    int q = q0 + ty, k = k0 + tx;
    if (q < N_ && k < N_)
        sc[(size_t)q*N_ + k] = s * scale;
}

// ---------------- row softmax over 196 ---------------------------------------
__global__ void softmax_kernel(int nrows)
{
    int gw = (blockIdx.x * blockDim.x + threadIdx.x) >> 5;
    if (gw >= nrows) return;
    int lane = threadIdx.x & 31;
    float* row = g_sc + (size_t)gw * N_;
    float vals[7];
    float mx = -1e30f;
#pragma unroll
    for (int i = 0; i < 7; i++) {
        int j = lane + 32*i;
        vals[i] = (j < N_) ? row[j] : -1e30f;
        mx = fmaxf(mx, vals[i]);
    }
#pragma unroll
    for (int o = 16; o > 0; o >>= 1) mx = fmaxf(mx, __shfl_xor_sync(0xffffffffu, mx, o));
    float sum = 0.f;
#pragma unroll
    for (int i = 0; i < 7; i++) { vals[i] = expf(vals[i] - mx); sum += vals[i]; }
#pragma unroll
    for (int o = 16; o > 0; o >>= 1) sum += __shfl_xor_sync(0xffffffffu, sum, o);
    float inv = 1.f / sum;
#pragma unroll
    for (int i = 0; i < 7; i++) {
        int j = lane + 32*i;
        if (j < N_) row[j] = vals[i] * inv;
    }
}

// ---------------- PV (batched over z) ----------------------------------------
__global__ void pv_kernel(const float* __restrict__ Vp, int vstride,
                          long vz, long oz, float* __restrict__ Out)
{
    int zz = blockIdx.y;
    int z  = zz >> 8;
    int bh = zz & 255;
    int b = bh >> 3, h = bh & 7;
    Vp  += (size_t)z * vz;
    Out += (size_t)z * oz;
    const float* P = g_sc + (size_t)zz * N_ * N_;
    int q0 = blockIdx.x * 32;
    __shared__ float Ps[32][17];
    __shared__ float Vs[16][64];
    int tid = threadIdx.x;
    int tx = tid & 63, ty = tid >> 6;
    float acc[8];
#pragma unroll
    for (int i = 0; i < 8; i++) acc[i] = 0.f;

    for (int k0 = 0; k0 < N_; k0 += 16) {
        {
            int pr = tid >> 3, pc = (tid & 7) * 2;
#pragma unroll
            for (int j = 0; j < 2; j++) {
                int q = q0 + pr, k = k0 + pc + j;
                Ps[pr][pc+j] = (q < N_ && k < N_) ? P[(size_t)q*N_ + k] : 0.f;
            }
        }
        {
            int vr = tid >> 4, vc = (tid & 15) * 4;
            int k = k0 + vr;
            float4 v = make_float4(0.f,0.f,0.f,0.f);
            if (k < N_) v = *reinterpret_cast<const float4*>(Vp + (size_t)(b*N_+k)*vstride + h*HD_ + vc);
            Vs[vr][vc]=v.x; Vs[vr][vc+1]=v.y; Vs[vr][vc+2]=v.z; Vs[vr][vc+3]=v.w;
        }
        __syncthreads();
#pragma unroll
        for (int kk = 0; kk < 16; kk++) {
            float vv = Vs[kk][tx];
#pragma unroll
            for (int i = 0; i < 8; i++)
                acc[i] += Ps[ty + 4*i][kk] * vv;
        }
        __syncthreads();
    }
#pragma unroll
    for (int i = 0; i < 8; i++) {
        int q = q0 + ty + 4*i;
        if (q < N_)
            Out[(size_t)(b*N_+q)*E_ + h*HD_ + tx] = acc[i];
    }
}

// ---------------- final LN of last token -> feat (B, 2E) ---------------------
__global__ void final_feat_kernel(const float* __restrict__ g,
                                  const float* __restrict__ b)
{
    int s = blockIdx.x >> 5;   // stream 0/1
    int bb = blockIdx.x & 31;  // batch
    const float* src = g_x + ((size_t)s*M_ + bb*N_ + (N_-1)) * E_;
    int tid = threadIdx.x;
    float v0 = src[tid], v1 = src[tid + 256];
    float ssum = v0 + v1, sq = v0*v0 + v1*v1;
#pragma unroll
    for (int o = 16; o > 0; o >>= 1) {
        ssum += __shfl_xor_sync(0xffffffffu, ssum, o);
        sq   += __shfl_xor_sync(0xffffffffu, sq,   o);
    }
    __shared__ float sh[16];
    int w = tid >> 5, lane = tid & 31;
    if (lane == 0) { sh[w] = ssum; sh[8+w] = sq; }
    __syncthreads();
    if (tid == 0) {
        float a = 0.f, c = 0.f;
        for (int i = 0; i < 8; i++) { a += sh[i]; c += sh[8+i]; }
        sh[0] = a; sh[8] = c;
    }
    __syncthreads();
    float mean = sh[0] * (1.f/E_);
    float var  = sh[8] * (1.f/E_) - mean*mean;
    float rs = rsqrtf(var + EPS_);
    float* dst = g_feat + (size_t)bb * (2*E_) + s*E_;
    dst[tid]       = (v0 - mean) * rs * g[tid]       + b[tid];
    dst[tid + 256] = (v1 - mean) * rs * g[tid + 256] + b[tid + 256];
}

// ---------------- host-side orchestration ------------------------------------
static inline void gemmB(const float* A, const float* W, const float* bias,
                         const float* res, float* C, int M, int N, int K,
                         int relu, int nz,
                         long sA, long sW, long sB, long sRes, long sC)
{
    dim3 grid((N + BN - 1)/BN, (M + BM - 1)/BM, nz);
    gemm_kernel<<<grid, 256>>>(A, W, bias, res, C, M, N, K, relu,
                               sA, sW, sB, sRes, sC);
}

extern "C" void kernel_launch(void* const* d_in, const int* in_sizes, int n_in,
                              void* d_out, int out_size)
{
    const float* image      = (const float*)d_in[0];
    const float* text_hidden= (const float*)d_in[1];
    const float* patch_ln_g = (const float*)d_in[2];
    const float* patch_ln_b = (const float*)d_in[3];
    const float* patch_w    = (const float*)d_in[4];
    const float* patch_b    = (const float*)d_in[5];
    const float* text_w     = (const float*)d_in[6];
    const float* text_b     = (const float*)d_in[7];
    const float* attn_in_w  = (const float*)d_in[8];
    const float* attn_in_b  = (const float*)d_in[9];
    const float* attn_out_w = (const float*)d_in[10];
    const float* attn_out_b = (const float*)d_in[11];
    const float* mlp_w1     = (const float*)d_in[12];
    const float* mlp_b1     = (const float*)d_in[13];
    const float* mlp_w2     = (const float*)d_in[14];
    const float* mlp_b2     = (const float*)d_in[15];
    const float* ln_gamma   = (const float*)d_in[16];
    const float* ln_beta    = (const float*)d_in[17];
    const float* fin_g      = (const float*)d_in[18];
    const float* fin_b      = (const float*)d_in[19];
    const float* cls_w1     = (const float*)d_in[20];
    const float* cls_b1     = (const float*)d_in[21];
    const float* cls_w2     = (const float*)d_in[22];
    const float* cls_b2     = (const float*)d_in[23];

    float *xp,*tp,*qkvp,*qp,*kvp,*aop,*hidp,*patchp,*featp,*clshp;
    cudaGetSymbolAddress((void**)&xp,    g_x);
    cudaGetSymbolAddress((void**)&tp,    g_t);
    cudaGetSymbolAddress((void**)&qkvp,  g_qkv);
    cudaGetSymbolAddress((void**)&qp,    g_q);
    cudaGetSymbolAddress((void**)&kvp,   g_kv);
    cudaGetSymbolAddress((void**)&aop,   g_ao);
    cudaGetSymbolAddress((void**)&hidp,  g_hid);
    cudaGetSymbolAddress((void**)&patchp,g_patch);
    cudaGetSymbolAddress((void**)&featp, g_feat);
    cudaGetSymbolAddress((void**)&clshp, g_clsh);

    float* x1p = xp;
    float* x2p = xp + (size_t)M_*E_;

    const float scale = 0.125f;  // 1/sqrt(64)
    dim3 sc_grid2(13, 13, 2*B_*H_);
    dim3 sc_grid1(13, 13, B_*H_);
    dim3 pv_grid2(7, 2*B_*H_);
    dim3 pv_grid1(7, B_*H_);
    int sm2 = (2*B_*H_*N_*32 + 127) / 128;
    int sm1 = (B_*H_*N_*32 + 127) / 128;

    // --- embedding ---
    patch_ln_kernel<<<M_, 256>>>(image, patch_ln_g, patch_ln_b);
    gemmB(patchp, patch_w, patch_b, nullptr, x1p, M_, E_, PD_, 0, 1, 0,0,0,0,0);
    gemmB(text_hidden, text_w, text_b, nullptr, x2p, M_, E_, 768, 0, 1, 0,0,0,0,0);
    posadd_kernel<<<(2*M_*E_ + 255)/256, 256>>>();

    for (int l = 0; l < L_; l++) {
        const float* g0 = ln_gamma + (size_t)(l*2+0)*E_;
        const float* b0 = ln_beta  + (size_t)(l*2+0)*E_;
        const float* g1 = ln_gamma + (size_t)(l*2+1)*E_;
        const float* b1 = ln_beta  + (size_t)(l*2+1)*E_;

        // --- self-attention, both streams batched (z = stream) ---
        {
            const float* wi = attn_in_w  + (size_t)(l*3)*1536*E_;
            const float* bi = attn_in_b  + (size_t)(l*3)*1536;
            const float* wo = attn_out_w + (size_t)(l*3)*E_*E_;
            const float* bo = attn_out_b + (size_t)(l*3)*E_;
            ln_kernel<<<2*M_, 256>>>(xp, g0, b0, tp);
            gemmB(tp, wi, bi, nullptr, qkvp, M_, 1536, E_, 0, 2,
                  (long)M_*E_, (long)1536*E_, 1536, 0, (long)M_*1536);
            scores_kernel<<<sc_grid2, 256>>>(qkvp, qkvp + E_, 1536, 1536,
                                             (long)M_*1536, (long)M_*1536, scale);
            softmax_kernel<<<sm2, 128>>>(2*B_*H_*N_);
            pv_kernel<<<pv_grid2, 256>>>(qkvp + 2*E_, 1536,
                                         (long)M_*1536, (long)M_*E_, aop);
            gemmB(aop, wo, bo, xp, xp, M_, E_, E_, 0, 2,
                  (long)M_*E_, (long)E_*E_, E_, (long)M_*E_, (long)M_*E_);
        }

        // --- guide attention: q from x2, kv from x1, overwrites x1 ---
        {
            const float* wi = attn_in_w  + (size_t)(l*3+2)*1536*E_;
            const float* bi = attn_in_b  + (size_t)(l*3+2)*1536;
            const float* wo = attn_out_w + (size_t)(l*3+2)*E_*E_;
            const float* bo = attn_out_b + (size_t)(l*3+2)*E_;
            gemmB(x2p, wi, bi, nullptr, qp, M_, E_, E_, 0, 1, 0,0,0,0,0);
            gemmB(x1p, wi + (size_t)E_*E_, bi + E_, nullptr, kvp, M_, 2*E_, E_, 0, 1, 0,0,0,0,0);
            scores_kernel<<<sc_grid1, 256>>>(qp, kvp, E_, 2*E_, 0, 0, scale);
            softmax_kernel<<<sm1, 128>>>(B_*H_*N_);
            pv_kernel<<<pv_grid1, 256>>>(kvp + E_, 2*E_, 0, 0, aop);
            gemmB(aop, wo, bo, nullptr, x1p, M_, E_, E_, 0, 1, 0,0,0,0,0);
        }

        // --- MLP, both streams in one M=12544 GEMM (shared weights) ---
        {
            const float* w1  = mlp_w1 + (size_t)l*4*E_*E_;
            const float* bb1 = mlp_b1 + (size_t)l*4*E_;
            const float* w2  = mlp_w2 + (size_t)l*E_*4*E_;
            const float* bb2 = mlp_b2 + (size_t)l*E_;
            ln_kernel<<<2*M_, 256>>>(xp, g1, b1, tp);
            gemmB(tp, w1, bb1, nullptr, hidp, 2*M_, 4*E_, E_, 1, 1, 0,0,0,0,0);
            gemmB(hidp, w2, bb2, xp, xp, 2*M_, E_, 4*E_, 0, 1, 0,0,0,0,0);
        }
    }

    // --- head ---
    final_feat_kernel<<<64, 256>>>(fin_g, fin_b);
    gemmB(featp, cls_w1, cls_b1, nullptr, clshp, B_, 4*E_, 2*E_, 1, 1, 0,0,0,0,0);
    gemmB(clshp, cls_w2, cls_b2, nullptr, (float*)d_out, B_, NCLS_, 4*E_, 0, 1, 0,0,0,0,0);
}

// round 6
// speedup vs baseline: 1.5067x; 1.4697x over previous
#include <cuda_runtime.h>
#include <cuda_bf16.h>
#include <math.h>
#include <stdint.h>

#define B_   32
#define N_   196
#define E_   512
#define H_   8
#define HD_  64
#define L_   4
#define M_   (B_*N_)          // 6272 tokens
#define PD_  3840             // patch dim
#define NCLS_ 101
#define EPS_ 1e-5f

// ---------------- scratch (device globals; no cudaMalloc allowed) ------------
__device__ float g_x[2*M_*E_];
__device__ float g_t[2*M_*E_];
__device__ float g_qkv[(size_t)2*M_*3*E_];
__device__ float g_q[M_*E_];
__device__ float g_kv[M_*2*E_];
__device__ float g_sc[(size_t)2*B_*H_*N_*N_];
__device__ float g_ao[2*M_*E_];
__device__ float g_hid[(size_t)2*M_*4*E_];
__device__ float g_patch[(size_t)M_*PD_];
__device__ float g_feat[B_*2*E_];
__device__ float g_clsh[B_*4*E_];

// ---------------- warp-MMA helpers (base compute_100-safe PTX) ---------------
__device__ __forceinline__ uint32_t smem_u32(const void* p) {
    uint32_t a;
    asm("{ .reg .u64 t; cvta.to.shared.u64 t, %1; cvt.u32.u64 %0, t; }" : "=r"(a) : "l"(p));
    return a;
}
__device__ __forceinline__ void ldm_x4(uint32_t addr, uint32_t* r) {
    asm volatile("ldmatrix.sync.aligned.m8n8.x4.shared.b16 {%0,%1,%2,%3}, [%4];"
        : "=r"(r[0]), "=r"(r[1]), "=r"(r[2]), "=r"(r[3]) : "r"(addr));
}
__device__ __forceinline__ void mma16816(float* c, const uint32_t* a, const uint32_t* b) {
    asm volatile("mma.sync.aligned.m16n8k16.row.col.f32.bf16.bf16.f32 "
        "{%0,%1,%2,%3}, {%4,%5,%6,%7}, {%8,%9}, {%0,%1,%2,%3};"
        : "+f"(c[0]), "+f"(c[1]), "+f"(c[2]), "+f"(c[3])
        : "r"(a[0]), "r"(a[1]), "r"(a[2]), "r"(a[3]), "r"(b[0]), "r"(b[1]));
}
// fp32 -> bf16 hi/lo split, packed as 2x (2 bf16) words
__device__ __forceinline__ void cvt_hilo(float4 v, uint32_t& hi0, uint32_t& hi1,
                                         uint32_t& lo0, uint32_t& lo1) {
    __nv_bfloat16 hx = __float2bfloat16(v.x);
    __nv_bfloat16 hy = __float2bfloat16(v.y);
    __nv_bfloat16 hz = __float2bfloat16(v.z);
    __nv_bfloat16 hw = __float2bfloat16(v.w);
    hi0 = ((uint32_t)__bfloat16_as_ushort(hy) << 16) | __bfloat16_as_ushort(hx);
    hi1 = ((uint32_t)__bfloat16_as_ushort(hw) << 16) | __bfloat16_as_ushort(hz);
    __nv_bfloat16 lx = __float2bfloat16(v.x - __bfloat162float(hx));
    __nv_bfloat16 ly = __float2bfloat16(v.y - __bfloat162float(hy));
    __nv_bfloat16 lz = __float2bfloat16(v.z - __bfloat162float(hz));
    __nv_bfloat16 lw = __float2bfloat16(v.w - __bfloat162float(hw));
    lo0 = ((uint32_t)__bfloat16_as_ushort(ly) << 16) | __bfloat16_as_ushort(lx);
    lo1 = ((uint32_t)__bfloat16_as_ushort(lw) << 16) | __bfloat16_as_ushort(lz);
}

// ======= tensor-core GEMM via mma.sync: C = act(A@W^T + bias [+res]) =========
// Tile 128x64, k-slab 32, double buffered. Requires M%128==0, N%64==0, K%32==0.
// smem per buffer (bf16, rows padded to 40 elems = 80B, 16B-aligned,
// conflict-free for ldmatrix): Ah 128x40, Al 128x40, Bh 64x40, Bl 64x40.
#define ROWB 80                         // padded row bytes
#define OFF_AL 10240
#define OFF_BH 20480
#define OFF_BL 25600
#define BUFB  30720
#define MMA_SMEM (2*BUFB)               // 61440 bytes

__global__ __launch_bounds__(256, 2)
void gemm_mma_kernel(const float* __restrict__ A, const float* __restrict__ W,
                     const float* __restrict__ bias, const float* __restrict__ res,
                     float* __restrict__ C, int M, int N, int K, int relu,
                     long sA, long sW, long sB, long sRes, long sC)
{
    int z = blockIdx.z;
    A += (size_t)z * sA;
    W += (size_t)z * sW;
    bias += (size_t)z * sB;
    if (res) res += (size_t)z * sRes;
    C += (size_t)z * sC;

    extern __shared__ char sm[];
    const uint32_t sbase = smem_u32(sm);
    const int tid = threadIdx.x, wid = tid >> 5, lane = tid & 31;
    const int m0 = blockIdx.y * 128, n0 = blockIdx.x * 64;
    const int wm = wid & 3, wn = wid >> 2;

    // gmem staging mapping
    const int aRow = tid >> 1, aCol = (tid & 1) * 16;   // A: 128 rows x 32 cols
    const int bRow = tid >> 2, bCol = (tid & 3) * 8;    // B: 64 rows x 32 cols
    const float* aG = A + (size_t)(m0 + aRow) * K + aCol;
    const float* bG = W + (size_t)(n0 + bRow) * K + bCol;
    const uint32_t aOff = (uint32_t)aRow * ROWB + aCol * 2;
    const uint32_t bOff = (uint32_t)bRow * ROWB + bCol * 2;

    float acc[2][4][4];
#pragma unroll
    for (int i = 0; i < 2; i++)
#pragma unroll
        for (int j = 0; j < 4; j++)
#pragma unroll
            for (int r = 0; r < 4; r++) acc[i][j][r] = 0.f;

    float4 aS[4], bS[2];
    // ldmatrix lane address components
    const uint32_t aLRow = (uint32_t)(wm * 32 + (lane & 7) + ((lane >> 3) & 1) * 8);
    const uint32_t aLCol = (uint32_t)((lane >> 4) * 8);
    const uint32_t bLRow = (uint32_t)(wn * 32 + (lane & 7) + (lane >> 4) * 8);
    const uint32_t bLCol = (uint32_t)(((lane >> 3) & 1) * 8);

    const int nslab = K >> 5;

    auto load_stage = [&](int s) {
        const float* ap = aG + s * 32;
        aS[0] = *reinterpret_cast<const float4*>(ap);
        aS[1] = *reinterpret_cast<const float4*>(ap + 4);
        aS[2] = *reinterpret_cast<const float4*>(ap + 8);
        aS[3] = *reinterpret_cast<const float4*>(ap + 12);
        const float* bp = bG + s * 32;
        bS[0] = *reinterpret_cast<const float4*>(bp);
        bS[1] = *reinterpret_cast<const float4*>(bp + 4);
    };
    auto store_stage = [&](int buf) {
        char* base = sm + buf * BUFB;
#pragma unroll
        for (int j = 0; j < 4; j++) {
            uint32_t h0, h1, l0, l1;
            cvt_hilo(aS[j], h0, h1, l0, l1);
            *reinterpret_cast<uint2*>(base + aOff + j * 8)          = make_uint2(h0, h1);
            *reinterpret_cast<uint2*>(base + OFF_AL + aOff + j * 8) = make_uint2(l0, l1);
        }
#pragma unroll
        for (int j = 0; j < 2; j++) {
            uint32_t h0, h1, l0, l1;
            cvt_hilo(bS[j], h0, h1, l0, l1);
            *reinterpret_cast<uint2*>(base + OFF_BH + bOff + j * 8) = make_uint2(h0, h1);
            *reinterpret_cast<uint2*>(base + OFF_BL + bOff + j * 8) = make_uint2(l0, l1);
        }
    };
    auto compute = [&](int buf) {
        uint32_t bb = sbase + buf * BUFB;
#pragma unroll
        for (int kk = 0; kk < 32; kk += 16) {
            uint32_t ah[2][4], al[2][4], bh[2][4], bl[2][4];
#pragma unroll
            for (int mt = 0; mt < 2; mt++) {
                uint32_t off = (aLRow + mt * 16) * ROWB + (kk + aLCol) * 2;
                ldm_x4(bb + off, ah[mt]);
                ldm_x4(bb + OFF_AL + off, al[mt]);
            }
#pragma unroll
            for (int nt2 = 0; nt2 < 2; nt2++) {
                uint32_t off = (bLRow + nt2 * 16) * ROWB + (kk + bLCol) * 2;
                ldm_x4(bb + OFF_BH + off, bh[nt2]);
                ldm_x4(bb + OFF_BL + off, bl[nt2]);
            }
#pragma unroll
            for (int mt = 0; mt < 2; mt++)
#pragma unroll
                for (int nt = 0; nt < 4; nt++) {
                    const uint32_t* bhp = &bh[nt >> 1][(nt & 1) * 2];
                    const uint32_t* blp = &bl[nt >> 1][(nt & 1) * 2];
                    mma16816(acc[mt][nt], ah[mt], bhp);
                    mma16816(acc[mt][nt], ah[mt], blp);
                    mma16816(acc[mt][nt], al[mt], bhp);
                }
        }
    };

    load_stage(0);
    store_stage(0);
    __syncthreads();
    for (int s = 1; s < nslab; s++) {
        load_stage(s);
        compute((s - 1) & 1);
        __syncthreads();
        store_stage(s & 1);
        __syncthreads();
    }
    compute((nslab - 1) & 1);

    // epilogue
#pragma unroll
    for (int mt = 0; mt < 2; mt++)
#pragma unroll
        for (int nt = 0; nt < 4; nt++) {
            int m = m0 + wm * 32 + mt * 16 + (lane >> 2);
            int n = n0 + wn * 32 + nt * 8 + (lane & 3) * 2;
            float b0 = bias[n], b1 = bias[n + 1];
#pragma unroll
            for (int half = 0; half < 2; half++) {
                int mm = m + half * 8;
                float v0 = acc[mt][nt][half * 2]     + b0;
                float v1 = acc[mt][nt][half * 2 + 1] + b1;
                if (res) {
                    float2 r2 = *reinterpret_cast<const float2*>(res + (size_t)mm * N + n);
                    v0 += r2.x; v1 += r2.y;
                }
                if (relu) { v0 = fmaxf(v0, 0.f); v1 = fmaxf(v1, 0.f); }
                *reinterpret_cast<float2*>(C + (size_t)mm * N + n) = make_float2(v0, v1);
            }
        }
}

// ------- fallback SIMT GEMM (head; any shape) --------------------------------
#define BM 128
#define BN 64
#define BK 16
__global__ __launch_bounds__(256, 2)
void gemm_kernel(const float* __restrict__ A,
                 const float* __restrict__ W,
                 const float* __restrict__ bias,
                 const float* __restrict__ res,
                 float* __restrict__ C,
                 int M, int N, int K, int relu)
{
    __shared__ float As[BK][BM+4];
    __shared__ float Ws[BK][BN+4];
    int tid = threadIdx.x;
    int tx = tid & 15, ty = tid >> 4;
    int m0 = blockIdx.y * BM, n0 = blockIdx.x * BN;
    float acc[8][4];
#pragma unroll
    for (int i = 0; i < 8; i++)
#pragma unroll
        for (int j = 0; j < 4; j++) acc[i][j] = 0.f;

    for (int k0 = 0; k0 < K; k0 += BK) {
#pragma unroll
        for (int t = 0; t < 2; t++) {
            int f = tid + t * 256;
            int r = f >> 2, kq = (f & 3) << 2;
            int m = m0 + r;
            float4 v = make_float4(0.f,0.f,0.f,0.f);
            if (m < M) v = *reinterpret_cast<const float4*>(A + (size_t)m*K + k0 + kq);
            As[kq][r]   = v.x; As[kq+1][r] = v.y;
            As[kq+2][r] = v.z; As[kq+3][r] = v.w;
        }
        {
            int r = tid >> 2, kq = (tid & 3) << 2;
            int n = n0 + r;
            float4 v = make_float4(0.f,0.f,0.f,0.f);
            if (n < N) v = *reinterpret_cast<const float4*>(W + (size_t)n*K + k0 + kq);
            Ws[kq][r]   = v.x; Ws[kq+1][r] = v.y;
            Ws[kq+2][r] = v.z; Ws[kq+3][r] = v.w;
        }
        __syncthreads();
#pragma unroll
        for (int kk = 0; kk < BK; kk++) {
            float a[8], b[4];
            *reinterpret_cast<float4*>(a)   = *reinterpret_cast<const float4*>(&As[kk][ty*8]);
            *reinterpret_cast<float4*>(a+4) = *reinterpret_cast<const float4*>(&As[kk][ty*8+4]);
            *reinterpret_cast<float4*>(b)   = *reinterpret_cast<const float4*>(&Ws[kk][tx*4]);
#pragma unroll
            for (int i = 0; i < 8; i++)
#pragma unroll
                for (int j = 0; j < 4; j++)
                    acc[i][j] += a[i]*b[j];
        }
        __syncthreads();
    }
#pragma unroll
    for (int i = 0; i < 8; i++) {
        int m = m0 + ty*8 + i;
        if (m >= M) continue;
#pragma unroll
        for (int j = 0; j < 4; j++) {
            int n = n0 + tx*4 + j;
            if (n >= N) continue;
            float v = acc[i][j] + bias[n];
            if (res) v += res[(size_t)m*N + n];
            if (relu) v = fmaxf(v, 0.f);
            C[(size_t)m*N + n] = v;
        }
    }
}

// ---------------- LayerNorm over 512 ----------------------------------------
__global__ void ln_kernel(const float* __restrict__ x,
                          const float* __restrict__ g,
                          const float* __restrict__ b,
                          float* __restrict__ y)
{
    int row = blockIdx.x;
    const float* xr = x + (size_t)row * E_;
    int tid = threadIdx.x;
    float v0 = xr[tid], v1 = xr[tid + 256];
    float s  = v0 + v1;
    float ss = v0*v0 + v1*v1;
#pragma unroll
    for (int o = 16; o > 0; o >>= 1) {
        s  += __shfl_xor_sync(0xffffffffu, s,  o);
        ss += __shfl_xor_sync(0xffffffffu, ss, o);
    }
    __shared__ float sh[16];
    int w = tid >> 5, lane = tid & 31;
    if (lane == 0) { sh[w] = s; sh[8+w] = ss; }
    __syncthreads();
    if (tid == 0) {
        float a = 0.f, c = 0.f;
        for (int i = 0; i < 8; i++) { a += sh[i]; c += sh[8+i]; }
        sh[0] = a; sh[8] = c;
    }
    __syncthreads();
    float mean = sh[0] * (1.f/E_);
    float var  = sh[8] * (1.f/E_) - mean*mean;
    float rs = rsqrtf(var + EPS_);
    float* yr = y + (size_t)row * E_;
    yr[tid]       = (v0 - mean) * rs * g[tid]       + b[tid];
    yr[tid + 256] = (v1 - mean) * rs * g[tid + 256] + b[tid + 256];
}

// ---------------- shifted-patch gather + LN(3840) ----------------------------
__global__ void patch_ln_kernel(const float* __restrict__ image,
                                const float* __restrict__ g,
                                const float* __restrict__ bb)
{
    __shared__ float buf[PD_];
    __shared__ float sh[16];
    int bn = blockIdx.x;
    int b  = bn / N_, n = bn % N_;
    int ph = n / 14, pw = n % 14;
    int tid = threadIdx.x;

    float s = 0.f, ss = 0.f;
    for (int d = tid; d < PD_; d += 256) {
        int c  = d % 15, t = d / 15;
        int p2 = t % 16, p1 = t / 16;
        int sh_idx = c / 3, ch = c % 3;
        int row = ph*16 + p1, col = pw*16 + p2;
        if      (sh_idx == 1) col -= 1;
        else if (sh_idx == 2) col += 1;
        else if (sh_idx == 3) row -= 1;
        else if (sh_idx == 4) row += 1;
        float v = 0.f;
        if (row >= 0 && row < 224 && col >= 0 && col < 224)
            v = image[(((size_t)b*3 + ch)*224 + row)*224 + col];
        buf[d] = v;
        s += v; ss += v*v;
    }
#pragma unroll
    for (int o = 16; o > 0; o >>= 1) {
        s  += __shfl_xor_sync(0xffffffffu, s,  o);
        ss += __shfl_xor_sync(0xffffffffu, ss, o);
    }
    int w = tid >> 5, lane = tid & 31;
    if (lane == 0) { sh[w] = s; sh[8+w] = ss; }
    __syncthreads();
    if (tid == 0) {
        float a = 0.f, c = 0.f;
        for (int i = 0; i < 8; i++) { a += sh[i]; c += sh[8+i]; }
        sh[0] = a; sh[8] = c;
    }
    __syncthreads();
    float mean = sh[0] * (1.f/PD_);
    float var  = sh[8] * (1.f/PD_) - mean*mean;
    float rs = rsqrtf(var + EPS_);
    float* out = g_patch + (size_t)bn * PD_;
    for (int d = tid; d < PD_; d += 256)
        out[d] = (buf[d] - mean) * rs * g[d] + bb[d];
}

// ---------------- positional add (buggy batch-indexed sinusoid, per ref) -----
__global__ void posadd_kernel()
{
    int idx = blockIdx.x * 256 + threadIdx.x;
    if (idx >= 2*M_*E_) return;
    int e = idx & (E_-1);
    int stream_rem = idx % (M_*E_);
    int b = stream_rem / (N_*E_);
    float p = (float)(b + 1);
    int i = e & 255;
    float f = expf(-(float)i * (9.210340371976184f / 255.0f));
    float ang = p * f;
    float v = (e < 256) ? sinf(ang) : cosf(ang);
    g_x[idx] += v;
}

// ---------------- attention: scores = scale * Q K^T  (batched over z) --------
__global__ void scores_kernel(const float* __restrict__ Qp,
                              const float* __restrict__ Kp,
                              int qstride, int kstride,
                              long qz, long kz, float scale)
{
    int zz = blockIdx.z;
    int z  = zz >> 8;
    int bh = zz & 255;
    int b = bh >> 3, h = bh & 7;
    Qp += (size_t)z * qz;
    Kp += (size_t)z * kz;
    float* sc = g_sc + (size_t)zz * N_ * N_;
    int q0 = blockIdx.y * 16, k0 = blockIdx.x * 16;
    __shared__ float qs[16][68];
    __shared__ float ks[16][68];
    int tid = threadIdx.x;
    int r = tid >> 4, c4 = (tid & 15) * 4;
    {
        int q = q0 + r;
        float4 v = make_float4(0.f,0.f,0.f,0.f);
        if (q < N_) v = *reinterpret_cast<const float4*>(Qp + (size_t)(b*N_+q)*qstride + h*HD_ + c4);
        qs[r][c4]=v.x; qs[r][c4+1]=v.y; qs[r][c4+2]=v.z; qs[r][c4+3]=v.w;
        int k = k0 + r;
        float4 w = make_float4(0.f,0.f,0.f,0.f);
        if (k < N_) w = *reinterpret_cast<const float4*>(Kp + (size_t)(b*N_+k)*kstride + h*HD_ + c4);
        ks[r][c4]=w.x; ks[r][c4+1]=w.y; ks[r][c4+2]=w.z; ks[r][c4+3]=w.w;
    }
    __syncthreads();
    int ty = tid >> 4, tx = tid & 15;
    float s = 0.f;
#pragma unroll
    for (int d = 0; d < HD_; d++) s += qs[ty][d] * ks[tx][d];
    int q = q0 + ty, k = k0 + tx;
    if (q < N_ && k < N_)
        sc[(size_t)q*N_ + k] = s * scale;
}

// ---------------- row softmax over 196 ---------------------------------------
__global__ void softmax_kernel(int nrows)
{
    int gw = (blockIdx.x * blockDim.x + threadIdx.x) >> 5;
    if (gw >= nrows) return;
    int lane = threadIdx.x & 31;
    float* row = g_sc + (size_t)gw * N_;
    float vals[7];
    float mx = -1e30f;
#pragma unroll
    for (int i = 0; i < 7; i++) {
        int j = lane + 32*i;
        vals[i] = (j < N_) ? row[j] : -1e30f;
        mx = fmaxf(mx, vals[i]);
    }
#pragma unroll
    for (int o = 16; o > 0; o >>= 1) mx = fmaxf(mx, __shfl_xor_sync(0xffffffffu, mx, o));
    float sum = 0.f;
#pragma unroll
    for (int i = 0; i < 7; i++) { vals[i] = expf(vals[i] - mx); sum += vals[i]; }
#pragma unroll
    for (int o = 16; o > 0; o >>= 1) sum += __shfl_xor_sync(0xffffffffu, sum, o);
    float inv = 1.f / sum;
#pragma unroll
    for (int i = 0; i < 7; i++) {
        int j = lane + 32*i;
        if (j < N_) row[j] = vals[i] * inv;
    }
}

// ---------------- PV (batched over z) ----------------------------------------
__global__ void pv_kernel(const float* __restrict__ Vp, int vstride,
                          long vz, long oz, float* __restrict__ Out)
{
    int zz = blockIdx.y;
    int z  = zz >> 8;
    int bh = zz & 255;
    int b = bh >> 3, h = bh & 7;
    Vp  += (size_t)z * vz;
    Out += (size_t)z * oz;
    const float* P = g_sc + (size_t)zz * N_ * N_;
    int q0 = blockIdx.x * 32;
    __shared__ float Ps[32][17];
    __shared__ float Vs[16][64];
    int tid = threadIdx.x;
    int tx = tid & 63, ty = tid >> 6;
    float acc[8];
#pragma unroll
    for (int i = 0; i < 8; i++) acc[i] = 0.f;

    for (int k0 = 0; k0 < N_; k0 += 16) {
        {
            int pr = tid >> 3, pc = (tid & 7) * 2;
#pragma unroll
            for (int j = 0; j < 2; j++) {
                int q = q0 + pr, k = k0 + pc + j;
                Ps[pr][pc+j] = (q < N_ && k < N_) ? P[(size_t)q*N_ + k] : 0.f;
            }
        }
        {
            int vr = tid >> 4, vc = (tid & 15) * 4;
            int k = k0 + vr;
            float4 v = make_float4(0.f,0.f,0.f,0.f);
            if (k < N_) v = *reinterpret_cast<const float4*>(Vp + (size_t)(b*N_+k)*vstride + h*HD_ + vc);
            Vs[vr][vc]=v.x; Vs[vr][vc+1]=v.y; Vs[vr][vc+2]=v.z; Vs[vr][vc+3]=v.w;
        }
        __syncthreads();
#pragma unroll
        for (int kk = 0; kk < 16; kk++) {
            float vv = Vs[kk][tx];
#pragma unroll
            for (int i = 0; i < 8; i++)
                acc[i] += Ps[ty + 4*i][kk] * vv;
        }
        __syncthreads();
    }
#pragma unroll
    for (int i = 0; i < 8; i++) {
        int q = q0 + ty + 4*i;
        if (q < N_)
            Out[(size_t)(b*N_+q)*E_ + h*HD_ + tx] = acc[i];
    }
}

// ---------------- final LN of last token -> feat (B, 2E) ---------------------
__global__ void final_feat_kernel(const float* __restrict__ g,
                                  const float* __restrict__ b)
{
    int s = blockIdx.x >> 5;
    int bb = blockIdx.x & 31;
    const float* src = g_x + ((size_t)s*M_ + bb*N_ + (N_-1)) * E_;
    int tid = threadIdx.x;
    float v0 = src[tid], v1 = src[tid + 256];
    float ssum = v0 + v1, sq = v0*v0 + v1*v1;
#pragma unroll
    for (int o = 16; o > 0; o >>= 1) {
        ssum += __shfl_xor_sync(0xffffffffu, ssum, o);
        sq   += __shfl_xor_sync(0xffffffffu, sq,   o);
    }
    __shared__ float sh[16];
    int w = tid >> 5, lane = tid & 31;
    if (lane == 0) { sh[w] = ssum; sh[8+w] = sq; }
    __syncthreads();
    if (tid == 0) {
        float a = 0.f, c = 0.f;
        for (int i = 0; i < 8; i++) { a += sh[i]; c += sh[8+i]; }
        sh[0] = a; sh[8] = c;
    }
    __syncthreads();
    float mean = sh[0] * (1.f/E_);
    float var  = sh[8] * (1.f/E_) - mean*mean;
    float rs = rsqrtf(var + EPS_);
    float* dst = g_feat + (size_t)bb * (2*E_) + s*E_;
    dst[tid]       = (v0 - mean) * rs * g[tid]       + b[tid];
    dst[tid + 256] = (v1 - mean) * rs * g[tid + 256] + b[tid + 256];
}

// ---------------- host-side orchestration ------------------------------------
static inline void gemmT(const float* A, const float* W, const float* bias,
                         const float* res, float* C, int M, int N, int K,
                         int relu, int nz,
                         long sA, long sW, long sB, long sRes, long sC)
{
    dim3 grid(N / 64, M / 128, nz);
    gemm_mma_kernel<<<grid, 256, MMA_SMEM>>>(A, W, bias, res, C, M, N, K, relu,
                                             sA, sW, sB, sRes, sC);
}
static inline void gemmS(const float* A, const float* W, const float* bias,
                         const float* res, float* C, int M, int N, int K, int relu)
{
    dim3 grid((N + BN - 1)/BN, (M + BM - 1)/BM);
    gemm_kernel<<<grid, 256>>>(A, W, bias, res, C, M, N, K, relu);
}

extern "C" void kernel_launch(void* const* d_in, const int* in_sizes, int n_in,
                              void* d_out, int out_size)
{
    const float* image      = (const float*)d_in[0];
    const float* text_hidden= (const float*)d_in[1];
    const float* patch_ln_g = (const float*)d_in[2];
    const float* patch_ln_b = (const float*)d_in[3];
    const float* patch_w    = (const float*)d_in[4];
    const float* patch_b    = (const float*)d_in[5];
    const float* text_w     = (const float*)d_in[6];
    const float* text_b     = (const float*)d_in[7];
    const float* attn_in_w  = (const float*)d_in[8];
    const float* attn_in_b  = (const float*)d_in[9];
    const float* attn_out_w = (const float*)d_in[10];
    const float* attn_out_b = (const float*)d_in[11];
    const float* mlp_w1     = (const float*)d_in[12];
    const float* mlp_b1     = (const float*)d_in[13];
    const float* mlp_w2     = (const float*)d_in[14];
    const float* mlp_b2     = (const float*)d_in[15];
    const float* ln_gamma   = (const float*)d_in[16];
    const float* ln_beta    = (const float*)d_in[17];
    const float* fin_g      = (const float*)d_in[18];
    const float* fin_b      = (const float*)d_in[19];
    const float* cls_w1     = (const float*)d_in[20];
    const float* cls_b1     = (const float*)d_in[21];
    const float* cls_w2     = (const float*)d_in[22];
    const float* cls_b2     = (const float*)d_in[23];

    cudaFuncSetAttribute(gemm_mma_kernel,
                         cudaFuncAttributeMaxDynamicSharedMemorySize, MMA_SMEM);

    float *xp,*tp,*qkvp,*qp,*kvp,*aop,*hidp,*patchp,*featp,*clshp;
    cudaGetSymbolAddress((void**)&xp,    g_x);
    cudaGetSymbolAddress((void**)&tp,    g_t);
    cudaGetSymbolAddress((void**)&qkvp,  g_qkv);
    cudaGetSymbolAddress((void**)&qp,    g_q);
    cudaGetSymbolAddress((void**)&kvp,   g_kv);
    cudaGetSymbolAddress((void**)&aop,   g_ao);
    cudaGetSymbolAddress((void**)&hidp,  g_hid);
    cudaGetSymbolAddress((void**)&patchp,g_patch);
    cudaGetSymbolAddress((void**)&featp, g_feat);
    cudaGetSymbolAddress((void**)&clshp, g_clsh);

    float* x1p = xp;
    float* x2p = xp + (size_t)M_*E_;

    const float scale = 0.125f;  // 1/sqrt(64)
    dim3 sc_grid2(13, 13, 2*B_*H_);
    dim3 sc_grid1(13, 13, B_*H_);
    dim3 pv_grid2(7, 2*B_*H_);
    dim3 pv_grid1(7, B_*H_);
    int sm2 = (2*B_*H_*N_*32 + 127) / 128;
    int sm1 = (B_*H_*N_*32 + 127) / 128;

    // --- embedding ---
    patch_ln_kernel<<<M_, 256>>>(image, patch_ln_g, patch_ln_b);
    gemmT(patchp, patch_w, patch_b, nullptr, x1p, M_, E_, PD_, 0, 1, 0,0,0,0,0);
    gemmT(text_hidden, text_w, text_b, nullptr, x2p, M_, E_, 768, 0, 1, 0,0,0,0,0);
    posadd_kernel<<<(2*M_*E_ + 255)/256, 256>>>();

    for (int l = 0; l < L_; l++) {
        const float* g0 = ln_gamma + (size_t)(l*2+0)*E_;
        const float* b0 = ln_beta  + (size_t)(l*2+0)*E_;
        const float* g1 = ln_gamma + (size_t)(l*2+1)*E_;
        const float* b1 = ln_beta  + (size_t)(l*2+1)*E_;

        // --- self-attention, both streams batched (z = stream) ---
        {
            const float* wi = attn_in_w  + (size_t)(l*3)*1536*E_;
            const float* bi = attn_in_b  + (size_t)(l*3)*1536;
            const float* wo = attn_out_w + (size_t)(l*3)*E_*E_;
            const float* bo = attn_out_b + (size_t)(l*3)*E_;
            ln_kernel<<<2*M_, 256>>>(xp, g0, b0, tp);
            gemmT(tp, wi, bi, nullptr, qkvp, M_, 1536, E_, 0, 2,
                  (long)M_*E_, (long)1536*E_, 1536, 0, (long)M_*1536);
            scores_kernel<<<sc_grid2, 256>>>(qkvp, qkvp + E_, 1536, 1536,
                                             (long)M_*1536, (long)M_*1536, scale);
            softmax_kernel<<<sm2, 128>>>(2*B_*H_*N_);
            pv_kernel<<<pv_grid2, 256>>>(qkvp + 2*E_, 1536,
                                         (long)M_*1536, (long)M_*E_, aop);
            gemmT(aop, wo, bo, xp, xp, M_, E_, E_, 0, 2,
                  (long)M_*E_, (long)E_*E_, E_, (long)M_*E_, (long)M_*E_);
        }

        // --- guide attention: q from x2, kv from x1, overwrites x1 ---
        {
            const float* wi = attn_in_w  + (size_t)(l*3+2)*1536*E_;
            const float* bi = attn_in_b  + (size_t)(l*3+2)*1536;
            const float* wo = attn_out_w + (size_t)(l*3+2)*E_*E_;
            const float* bo = attn_out_b + (size_t)(l*3+2)*E_;
            gemmT(x2p, wi, bi, nullptr, qp, M_, E_, E_, 0, 1, 0,0,0,0,0);
            gemmT(x1p, wi + (size_t)E_*E_, bi + E_, nullptr, kvp, M_, 2*E_, E_, 0, 1, 0,0,0,0,0);
            scores_kernel<<<sc_grid1, 256>>>(qp, kvp, E_, 2*E_, 0, 0, scale);
            softmax_kernel<<<sm1, 128>>>(B_*H_*N_);
            pv_kernel<<<pv_grid1, 256>>>(kvp + E_, 2*E_, 0, 0, aop);
            gemmT(aop, wo, bo, nullptr, x1p, M_, E_, E_, 0, 1, 0,0,0,0,0);
        }

        // --- MLP, both streams in one M=12544 GEMM (shared weights) ---
        {
            const float* w1  = mlp_w1 + (size_t)l*4*E_*E_;
            const float* bb1 = mlp_b1 + (size_t)l*4*E_;
            const float* w2  = mlp_w2 + (size_t)l*E_*4*E_;
            const float* bb2 = mlp_b2 + (size_t)l*E_;
            ln_kernel<<<2*M_, 256>>>(xp, g1, b1, tp);
            gemmT(tp, w1, bb1, nullptr, hidp, 2*M_, 4*E_, E_, 1, 1, 0,0,0,0,0);
            gemmT(hidp, w2, bb2, xp, xp, 2*M_, E_, 4*E_, 0, 1, 0,0,0,0,0);
        }
    }

    // --- head (tiny; SIMT path) ---
    final_feat_kernel<<<64, 256>>>(fin_g, fin_b);
    gemmS(featp, cls_w1, cls_b1, nullptr, clshp, B_, 4*E_, 2*E_, 1);
    gemmS(clshp, cls_w2, cls_b2, nullptr, (float*)d_out, B_, NCLS_, 4*E_, 0);
}

// round 7
// speedup vs baseline: 1.7294x; 1.1478x over previous
#include <cuda_runtime.h>
#include <cuda_bf16.h>
#include <math.h>
#include <stdint.h>

#define B_   32
#define N_   196
#define E_   512
#define H_   8
#define HD_  64
#define L_   4
#define M_   (B_*N_)          // 6272 tokens
#define PD_  3840             // patch dim
#define NCLS_ 101
#define EPS_ 1e-5f

// ---------------- scratch (device globals; no cudaMalloc allowed) ------------
__device__ float g_x[2*M_*E_];
__device__ float g_t[2*M_*E_];
__device__ float g_qkv[(size_t)2*M_*3*E_];
__device__ float g_q[M_*E_];
__device__ float g_kv[M_*2*E_];
__device__ float g_sc[(size_t)2*B_*H_*N_*N_];
__device__ float g_ao[2*M_*E_];
__device__ float g_hid[(size_t)2*M_*4*E_];
__device__ float g_patch[(size_t)M_*PD_];
__device__ float g_feat[B_*2*E_];
__device__ float g_clsh[B_*4*E_];
// bf16 hi/lo split buffers (A: up to 12544x2048 elems; W: up to 2x1536x512)
#define MAXA_W 12845056   // (12544*2048)/2 uint32 words
#define MAXW_W 786432     // (2*1536*512)/2
__device__ uint32_t g_bfAhi[MAXA_W];
__device__ uint32_t g_bfAlo[MAXA_W];
__device__ uint32_t g_bfWhi[MAXW_W];
__device__ uint32_t g_bfWlo[MAXW_W];

// ---------------- PTX helpers (base compute_100-safe) ------------------------
__device__ __forceinline__ uint32_t smem_u32(const void* p) {
    uint32_t a;
    asm("{ .reg .u64 t; cvta.to.shared.u64 t, %1; cvt.u32.u64 %0, t; }" : "=r"(a) : "l"(p));
    return a;
}
__device__ __forceinline__ void ldm_x4(uint32_t addr, uint32_t* r) {
    asm volatile("ldmatrix.sync.aligned.m8n8.x4.shared.b16 {%0,%1,%2,%3}, [%4];"
        : "=r"(r[0]), "=r"(r[1]), "=r"(r[2]), "=r"(r[3]) : "r"(addr));
}
__device__ __forceinline__ void mma16816(float* c, const uint32_t* a, const uint32_t* b) {
    asm volatile("mma.sync.aligned.m16n8k16.row.col.f32.bf16.bf16.f32 "
        "{%0,%1,%2,%3}, {%4,%5,%6,%7}, {%8,%9}, {%0,%1,%2,%3};"
        : "+f"(c[0]), "+f"(c[1]), "+f"(c[2]), "+f"(c[3])
        : "r"(a[0]), "r"(a[1]), "r"(a[2]), "r"(a[3]), "r"(b[0]), "r"(b[1]));
}
__device__ __forceinline__ void cp16(uint32_t dst, const void* src) {
    asm volatile("cp.async.ca.shared.global [%0], [%1], 16;" :: "r"(dst), "l"(src));
}
#define CP_COMMIT() asm volatile("cp.async.commit_group;" ::: "memory")
#define CP_WAIT1()  asm volatile("cp.async.wait_group 1;" ::: "memory")

// fp32x4 -> bf16 hi/lo split, packed pairs
__device__ __forceinline__ void cvt_hilo(float4 v, uint32_t& hi0, uint32_t& hi1,
                                         uint32_t& lo0, uint32_t& lo1) {
    __nv_bfloat16 hx = __float2bfloat16(v.x);
    __nv_bfloat16 hy = __float2bfloat16(v.y);
    __nv_bfloat16 hz = __float2bfloat16(v.z);
    __nv_bfloat16 hw = __float2bfloat16(v.w);
    hi0 = ((uint32_t)__bfloat16_as_ushort(hy) << 16) | __bfloat16_as_ushort(hx);
    hi1 = ((uint32_t)__bfloat16_as_ushort(hw) << 16) | __bfloat16_as_ushort(hz);
    __nv_bfloat16 lx = __float2bfloat16(v.x - __bfloat162float(hx));
    __nv_bfloat16 ly = __float2bfloat16(v.y - __bfloat162float(hy));
    __nv_bfloat16 lz = __float2bfloat16(v.z - __bfloat162float(hz));
    __nv_bfloat16 lw = __float2bfloat16(v.w - __bfloat162float(hw));
    lo0 = ((uint32_t)__bfloat16_as_ushort(ly) << 16) | __bfloat16_as_ushort(lx);
    lo1 = ((uint32_t)__bfloat16_as_ushort(lw) << 16) | __bfloat16_as_ushort(lz);
}

// ---------------- split: fp32 -> bf16 hi + lo (bandwidth-bound) --------------
__global__ void split_kernel(const float4* __restrict__ in,
                             uint2* __restrict__ hi, uint2* __restrict__ lo, long n4)
{
    long i = (long)blockIdx.x * blockDim.x + threadIdx.x;
    if (i >= n4) return;
    float4 v = in[i];
    uint32_t h0, h1, l0, l1;
    cvt_hilo(v, h0, h1, l0, l1);
    hi[i] = make_uint2(h0, h1);
    lo[i] = make_uint2(l0, l1);
}

// ======= bf16 tensor-core GEMM: C = act(A@W^T + bias [+res]), z-batched ======
// Pre-split bf16 inputs. Tile 128x128, k-slab 32, 3-stage cp.async pipeline.
// Requires M%128==0, N%128==0, K%32==0.
#define ROWB 80
#define HOFF 10240                 // bytes per operand-half (128 rows x 80B)
#define OFF_AL (1*HOFF)
#define OFF_BH (2*HOFF)
#define OFF_BL (3*HOFF)
#define BUFB   (4*HOFF)            // 40960
#define GSMEM  (3*BUFB)            // 122880

__global__ __launch_bounds__(256, 1)
void gemm_bf16_kernel(const __nv_bfloat16* __restrict__ Ahi,
                      const __nv_bfloat16* __restrict__ Alo,
                      const __nv_bfloat16* __restrict__ Bhi,
                      const __nv_bfloat16* __restrict__ Blo,
                      const float* __restrict__ bias,
                      const float* __restrict__ res,
                      float* __restrict__ C,
                      int M, int N, int K, int relu,
                      long sA, long sW, long sB, long sRes, long sC)
{
    int z = blockIdx.z;
    Ahi += (size_t)z * sA;  Alo += (size_t)z * sA;
    Bhi += (size_t)z * sW;  Blo += (size_t)z * sW;
    bias += (size_t)z * sB;
    if (res) res += (size_t)z * sRes;
    C += (size_t)z * sC;

    extern __shared__ char sm[];
    const uint32_t sbase = smem_u32(sm);
    const int tid = threadIdx.x, wid = tid >> 5, lane = tid & 31;
    const int m0 = blockIdx.y * 128, n0 = blockIdx.x * 128;
    const int wm = wid >> 2, wn = wid & 3;       // 2 x 4 warp grid; warp tile 64x32

    float acc[4][4][4];
#pragma unroll
    for (int i = 0; i < 4; i++)
#pragma unroll
        for (int j = 0; j < 4; j++)
#pragma unroll
            for (int r = 0; r < 4; r++) acc[i][j][r] = 0.f;

    // cp.async mapping: 512 16B-chunks per operand-half; 2 per thread per half
    const int c0row = tid >> 2, c0c = (tid & 3);
    const int c1row = (tid + 256) >> 2, c1c = ((tid + 256) & 3);

    auto issue = [&](int s, int buf) {
        uint32_t base = sbase + buf * BUFB;
        long kb = (long)s * 32;
        {
            const __nv_bfloat16* a0h = Ahi + (size_t)(m0 + c0row) * K + kb + c0c * 8;
            const __nv_bfloat16* a0l = Alo + (size_t)(m0 + c0row) * K + kb + c0c * 8;
            const __nv_bfloat16* a1h = Ahi + (size_t)(m0 + c1row) * K + kb + c1c * 8;
            const __nv_bfloat16* a1l = Alo + (size_t)(m0 + c1row) * K + kb + c1c * 8;
            cp16(base + c0row * ROWB + c0c * 16, a0h);
            cp16(base + OFF_AL + c0row * ROWB + c0c * 16, a0l);
            cp16(base + c1row * ROWB + c1c * 16, a1h);
            cp16(base + OFF_AL + c1row * ROWB + c1c * 16, a1l);
        }
        {
            const __nv_bfloat16* b0h = Bhi + (size_t)(n0 + c0row) * K + kb + c0c * 8;
            const __nv_bfloat16* b0l = Blo + (size_t)(n0 + c0row) * K + kb + c0c * 8;
            const __nv_bfloat16* b1h = Bhi + (size_t)(n0 + c1row) * K + kb + c1c * 8;
            const __nv_bfloat16* b1l = Blo + (size_t)(n0 + c1row) * K + kb + c1c * 8;
            cp16(base + OFF_BH + c0row * ROWB + c0c * 16, b0h);
            cp16(base + OFF_BL + c0row * ROWB + c0c * 16, b0l);
            cp16(base + OFF_BH + c1row * ROWB + c1c * 16, b1h);
            cp16(base + OFF_BL + c1row * ROWB + c1c * 16, b1l);
        }
    };

    // ldmatrix lane components
    const uint32_t aR = (uint32_t)(wm * 64 + (lane & 7) + ((lane >> 3) & 1) * 8);
    const uint32_t aC = (uint32_t)((lane >> 4) * 8);
    const uint32_t bR = (uint32_t)(wn * 32 + (lane & 7) + (lane >> 4) * 8);
    const uint32_t bC = (uint32_t)(((lane >> 3) & 1) * 8);

    auto compute = [&](int buf) {
        uint32_t bb = sbase + buf * BUFB;
#pragma unroll
        for (int kk = 0; kk < 32; kk += 16) {
            uint32_t ah[4][4], al[4][4], bh[2][4], bl[2][4];
#pragma unroll
            for (int mt = 0; mt < 4; mt++) {
                uint32_t off = (aR + mt * 16) * ROWB + (kk + aC) * 2;
                ldm_x4(bb + off, ah[mt]);
                ldm_x4(bb + OFF_AL + off, al[mt]);
            }
#pragma unroll
            for (int nt2 = 0; nt2 < 2; nt2++) {
                uint32_t off = (bR + nt2 * 16) * ROWB + (kk + bC) * 2;
                ldm_x4(bb + OFF_BH + off, bh[nt2]);
                ldm_x4(bb + OFF_BL + off, bl[nt2]);
            }
#pragma unroll
            for (int mt = 0; mt < 4; mt++)
#pragma unroll
                for (int nt = 0; nt < 4; nt++) {
                    const uint32_t* bhp = &bh[nt >> 1][(nt & 1) * 2];
                    const uint32_t* blp = &bl[nt >> 1][(nt & 1) * 2];
                    mma16816(acc[mt][nt], ah[mt], bhp);
                    mma16816(acc[mt][nt], ah[mt], blp);
                    mma16816(acc[mt][nt], al[mt], bhp);
                }
        }
    };

    const int nslab = K >> 5;
    issue(0, 0); CP_COMMIT();
    issue(1, 1); CP_COMMIT();
    for (int s = 0; s < nslab; s++) {
        CP_WAIT1();
        __syncthreads();
        if (s + 2 < nslab) issue(s + 2, (s + 2) % 3);
        CP_COMMIT();
        compute(s % 3);
    }

    // epilogue
#pragma unroll
    for (int mt = 0; mt < 4; mt++)
#pragma unroll
        for (int nt = 0; nt < 4; nt++) {
            int m = m0 + wm * 64 + mt * 16 + (lane >> 2);
            int n = n0 + wn * 32 + nt * 8 + (lane & 3) * 2;
            float b0 = bias[n], b1 = bias[n + 1];
#pragma unroll
            for (int half = 0; half < 2; half++) {
                int mm = m + half * 8;
                float v0 = acc[mt][nt][half * 2]     + b0;
                float v1 = acc[mt][nt][half * 2 + 1] + b1;
                if (res) {
                    float2 r2 = *reinterpret_cast<const float2*>(res + (size_t)mm * N + n);
                    v0 += r2.x; v1 += r2.y;
                }
                if (relu) { v0 = fmaxf(v0, 0.f); v1 = fmaxf(v1, 0.f); }
                *reinterpret_cast<float2*>(C + (size_t)mm * N + n) = make_float2(v0, v1);
            }
        }
}

// ------- fallback SIMT GEMM (head; any shape) --------------------------------
#define BM 128
#define BN 64
#define BK 16
__global__ __launch_bounds__(256, 2)
void gemm_kernel(const float* __restrict__ A,
                 const float* __restrict__ W,
                 const float* __restrict__ bias,
                 const float* __restrict__ res,
                 float* __restrict__ C,
                 int M, int N, int K, int relu)
{
    __shared__ float As[BK][BM+4];
    __shared__ float Ws[BK][BN+4];
    int tid = threadIdx.x;
    int tx = tid & 15, ty = tid >> 4;
    int m0 = blockIdx.y * BM, n0 = blockIdx.x * BN;
    float acc[8][4];
#pragma unroll
    for (int i = 0; i < 8; i++)
#pragma unroll
        for (int j = 0; j < 4; j++) acc[i][j] = 0.f;

    for (int k0 = 0; k0 < K; k0 += BK) {
#pragma unroll
        for (int t = 0; t < 2; t++) {
            int f = tid + t * 256;
            int r = f >> 2, kq = (f & 3) << 2;
            int m = m0 + r;
            float4 v = make_float4(0.f,0.f,0.f,0.f);
            if (m < M) v = *reinterpret_cast<const float4*>(A + (size_t)m*K + k0 + kq);
            As[kq][r]   = v.x; As[kq+1][r] = v.y;
            As[kq+2][r] = v.z; As[kq+3][r] = v.w;
        }
        {
            int r = tid >> 2, kq = (tid & 3) << 2;
            int n = n0 + r;
            float4 v = make_float4(0.f,0.f,0.f,0.f);
            if (n < N) v = *reinterpret_cast<const float4*>(W + (size_t)n*K + k0 + kq);
            Ws[kq][r]   = v.x; Ws[kq+1][r] = v.y;
            Ws[kq+2][r] = v.z; Ws[kq+3][r] = v.w;
        }
        __syncthreads();
#pragma unroll
        for (int kk = 0; kk < BK; kk++) {
            float a[8], b[4];
            *reinterpret_cast<float4*>(a)   = *reinterpret_cast<const float4*>(&As[kk][ty*8]);
            *reinterpret_cast<float4*>(a+4) = *reinterpret_cast<const float4*>(&As[kk][ty*8+4]);
            *reinterpret_cast<float4*>(b)   = *reinterpret_cast<const float4*>(&Ws[kk][tx*4]);
#pragma unroll
            for (int i = 0; i < 8; i++)
#pragma unroll
                for (int j = 0; j < 4; j++)
                    acc[i][j] += a[i]*b[j];
        }
        __syncthreads();
    }
#pragma unroll
    for (int i = 0; i < 8; i++) {
        int m = m0 + ty*8 + i;
        if (m >= M) continue;
#pragma unroll
        for (int j = 0; j < 4; j++) {
            int n = n0 + tx*4 + j;
            if (n >= N) continue;
            float v = acc[i][j] + bias[n];
            if (res) v += res[(size_t)m*N + n];
            if (relu) v = fmaxf(v, 0.f);
            C[(size_t)m*N + n] = v;
        }
    }
}

// ---------------- LayerNorm over 512 ----------------------------------------
__global__ void ln_kernel(const float* __restrict__ x,
                          const float* __restrict__ g,
                          const float* __restrict__ b,
                          float* __restrict__ y)
{
    int row = blockIdx.x;
    const float* xr = x + (size_t)row * E_;
    int tid = threadIdx.x;
    float v0 = xr[tid], v1 = xr[tid + 256];
    float s  = v0 + v1;
    float ss = v0*v0 + v1*v1;
#pragma unroll
    for (int o = 16; o > 0; o >>= 1) {
        s  += __shfl_xor_sync(0xffffffffu, s,  o);
        ss += __shfl_xor_sync(0xffffffffu, ss, o);
    }
    __shared__ float sh[16];
    int w = tid >> 5, lane = tid & 31;
    if (lane == 0) { sh[w] = s; sh[8+w] = ss; }
    __syncthreads();
    if (tid == 0) {
        float a = 0.f, c = 0.f;
        for (int i = 0; i < 8; i++) { a += sh[i]; c += sh[8+i]; }
        sh[0] = a; sh[8] = c;
    }
    __syncthreads();
    float mean = sh[0] * (1.f/E_);
    float var  = sh[8] * (1.f/E_) - mean*mean;
    float rs = rsqrtf(var + EPS_);
    float* yr = y + (size_t)row * E_;
    yr[tid]       = (v0 - mean) * rs * g[tid]       + b[tid];
    yr[tid + 256] = (v1 - mean) * rs * g[tid + 256] + b[tid + 256];
}

// ---------------- shifted-patch gather + LN(3840) ----------------------------
__global__ void patch_ln_kernel(const float* __restrict__ image,
                                const float* __restrict__ g,
                                const float* __restrict__ bb)
{
    __shared__ float buf[PD_];
    __shared__ float sh[16];
    int bn = blockIdx.x;
    int b  = bn / N_, n = bn % N_;
    int ph = n / 14, pw = n % 14;
    int tid = threadIdx.x;

    float s = 0.f, ss = 0.f;
    for (int d = tid; d < PD_; d += 256) {
        int c  = d % 15, t = d / 15;
        int p2 = t % 16, p1 = t / 16;
        int sh_idx = c / 3, ch = c % 3;
        int row = ph*16 + p1, col = pw*16 + p2;
        if      (sh_idx == 1) col -= 1;
        else if (sh_idx == 2) col += 1;
        else if (sh_idx == 3) row -= 1;
        else if (sh_idx == 4) row += 1;
        float v = 0.f;
        if (row >= 0 && row < 224 && col >= 0 && col < 224)
            v = image[(((size_t)b*3 + ch)*224 + row)*224 + col];
        buf[d] = v;
        s += v; ss += v*v;
    }
#pragma unroll
    for (int o = 16; o > 0; o >>= 1) {
        s  += __shfl_xor_sync(0xffffffffu, s,  o);
        ss += __shfl_xor_sync(0xffffffffu, ss, o);
    }
    int w = tid >> 5, lane = tid & 31;
    if (lane == 0) { sh[w] = s; sh[8+w] = ss; }
    __syncthreads();
    if (tid == 0) {
        float a = 0.f, c = 0.f;
        for (int i = 0; i < 8; i++) { a += sh[i]; c += sh[8+i]; }
        sh[0] = a; sh[8] = c;
    }
    __syncthreads();
    float mean = sh[0] * (1.f/PD_);
    float var  = sh[8] * (1.f/PD_) - mean*mean;
    float rs = rsqrtf(var + EPS_);
    float* out = g_patch + (size_t)bn * PD_;
    for (int d = tid; d < PD_; d += 256)
        out[d] = (buf[d] - mean) * rs * g[d] + bb[d];
}

// ---------------- positional add (buggy batch-indexed sinusoid, per ref) -----
__global__ void posadd_kernel()
{
    int idx = blockIdx.x * 256 + threadIdx.x;
    if (idx >= 2*M_*E_) return;
    int e = idx & (E_-1);
    int stream_rem = idx % (M_*E_);
    int b = stream_rem / (N_*E_);
    float p = (float)(b + 1);
    int i = e & 255;
    float f = expf(-(float)i * (9.210340371976184f / 255.0f));
    float ang = p * f;
    float v = (e < 256) ? sinf(ang) : cosf(ang);
    g_x[idx] += v;
}

// ---------------- attention: scores = scale * Q K^T  (batched over z) --------
__global__ void scores_kernel(const float* __restrict__ Qp,
                              const float* __restrict__ Kp,
                              int qstride, int kstride,
                              long qz, long kz, float scale)
{
    int zz = blockIdx.z;
    int z  = zz >> 8;
    int bh = zz & 255;
    int b = bh >> 3, h = bh & 7;
    Qp += (size_t)z * qz;
    Kp += (size_t)z * kz;
    float* sc = g_sc + (size_t)zz * N_ * N_;
    int q0 = blockIdx.y * 16, k0 = blockIdx.x * 16;
    __shared__ float qs[16][68];
    __shared__ float ks[16][68];
    int tid = threadIdx.x;
    int r = tid >> 4, c4 = (tid & 15) * 4;
    {
        int q = q0 + r;
        float4 v = make_float4(0.f,0.f,0.f,0.f);
        if (q < N_) v = *reinterpret_cast<const float4*>(Qp + (size_t)(b*N_+q)*qstride + h*HD_ + c4);
        qs[r][c4]=v.x; qs[r][c4+1]=v.y; qs[r][c4+2]=v.z; qs[r][c4+3]=v.w;
        int k = k0 + r;
        float4 w = make_float4(0.f,0.f,0.f,0.f);
        if (k < N_) w = *reinterpret_cast<const float4*>(Kp + (size_t)(b*N_+k)*kstride + h*HD_ + c4);
        ks[r][c4]=w.x; ks[r][c4+1]=w.y; ks[r][c4+2]=w.z; ks[r][c4+3]=w.w;
    }
    __syncthreads();
    int ty = tid >> 4, tx = tid & 15;
    float s = 0.f;
#pragma unroll
    for (int d = 0; d < HD_; d++) s += qs[ty][d] * ks[tx][d];
    int q = q0 + ty, k = k0 + tx;
    if (q < N_ && k < N_)
        sc[(size_t)q*N_ + k] = s * scale;
}

// ---------------- row softmax over 196 ---------------------------------------
__global__ void softmax_kernel(int nrows)
{
    int gw = (blockIdx.x * blockDim.x + threadIdx.x) >> 5;
    if (gw >= nrows) return;
    int lane = threadIdx.x & 31;
    float* row = g_sc + (size_t)gw * N_;
    float vals[7];
    float mx = -1e30f;
#pragma unroll
    for (int i = 0; i < 7; i++) {
        int j = lane + 32*i;
        vals[i] = (j < N_) ? row[j] : -1e30f;
        mx = fmaxf(mx, vals[i]);
    }
#pragma unroll
    for (int o = 16; o > 0; o >>= 1) mx = fmaxf(mx, __shfl_xor_sync(0xffffffffu, mx, o));
    float sum = 0.f;
#pragma unroll
    for (int i = 0; i < 7; i++) { vals[i] = expf(vals[i] - mx); sum += vals[i]; }
#pragma unroll
    for (int o = 16; o > 0; o >>= 1) sum += __shfl_xor_sync(0xffffffffu, sum, o);
    float inv = 1.f / sum;
#pragma unroll
    for (int i = 0; i < 7; i++) {
        int j = lane + 32*i;
        if (j < N_) row[j] = vals[i] * inv;
    }
}

// ---------------- PV (batched over z) ----------------------------------------
__global__ void pv_kernel(const float* __restrict__ Vp, int vstride,
                          long vz, long oz, float* __restrict__ Out)
{
    int zz = blockIdx.y;
    int z  = zz >> 8;
    int bh = zz & 255;
    int b = bh >> 3, h = bh & 7;
    Vp  += (size_t)z * vz;
    Out += (size_t)z * oz;
    const float* P = g_sc + (size_t)zz * N_ * N_;
    int q0 = blockIdx.x * 32;
    __shared__ float Ps[32][17];
    __shared__ float Vs[16][64];
    int tid = threadIdx.x;
    int tx = tid & 63, ty = tid >> 6;
    float acc[8];
#pragma unroll
    for (int i = 0; i < 8; i++) acc[i] = 0.f;

    for (int k0 = 0; k0 < N_; k0 += 16) {
        {
            int pr = tid >> 3, pc = (tid & 7) * 2;
#pragma unroll
            for (int j = 0; j < 2; j++) {
                int q = q0 + pr, k = k0 + pc + j;
                Ps[pr][pc+j] = (q < N_ && k < N_) ? P[(size_t)q*N_ + k] : 0.f;
            }
        }
        {
            int vr = tid >> 4, vc = (tid & 15) * 4;
            int k = k0 + vr;
            float4 v = make_float4(0.f,0.f,0.f,0.f);
            if (k < N_) v = *reinterpret_cast<const float4*>(Vp + (size_t)(b*N_+k)*vstride + h*HD_ + vc);
            Vs[vr][vc]=v.x; Vs[vr][vc+1]=v.y; Vs[vr][vc+2]=v.z; Vs[vr][vc+3]=v.w;
        }
        __syncthreads();
#pragma unroll
        for (int kk = 0; kk < 16; kk++) {
            float vv = Vs[kk][tx];
#pragma unroll
            for (int i = 0; i < 8; i++)
                acc[i] += Ps[ty + 4*i][kk] * vv;
        }
        __syncthreads();
    }
#pragma unroll
    for (int i = 0; i < 8; i++) {
        int q = q0 + ty + 4*i;
        if (q < N_)
            Out[(size_t)(b*N_+q)*E_ + h*HD_ + tx] = acc[i];
    }
}

// ---------------- final LN of last token -> feat (B, 2E) ---------------------
__global__ void final_feat_kernel(const float* __restrict__ g,
                                  const float* __restrict__ b)
{
    int s = blockIdx.x >> 5;
    int bb = blockIdx.x & 31;
    const float* src = g_x + ((size_t)s*M_ + bb*N_ + (N_-1)) * E_;
    int tid = threadIdx.x;
    float v0 = src[tid], v1 = src[tid + 256];
    float ssum = v0 + v1, sq = v0*v0 + v1*v1;
#pragma unroll
    for (int o = 16; o > 0; o >>= 1) {
        ssum += __shfl_xor_sync(0xffffffffu, ssum, o);
        sq   += __shfl_xor_sync(0xffffffffu, sq,   o);
    }
    __shared__ float sh[16];
    int w = tid >> 5, lane = tid & 31;
    if (lane == 0) { sh[w] = ssum; sh[8+w] = sq; }
    __syncthreads();
    if (tid == 0) {
        float a = 0.f, c = 0.f;
        for (int i = 0; i < 8; i++) { a += sh[i]; c += sh[8+i]; }
        sh[0] = a; sh[8] = c;
    }
    __syncthreads();
    float mean = sh[0] * (1.f/E_);
    float var  = sh[8] * (1.f/E_) - mean*mean;
    float rs = rsqrtf(var + EPS_);
    float* dst = g_feat + (size_t)bb * (2*E_) + s*E_;
    dst[tid]       = (v0 - mean) * rs * g[tid]       + b[tid];
    dst[tid + 256] = (v1 - mean) * rs * g[tid + 256] + b[tid + 256];
}

// ---------------- host-side orchestration ------------------------------------
static uint32_t *h_Ahi, *h_Alo, *h_Whi, *h_Wlo;

static inline void splitA(const float* src, size_t n)
{
    long n4 = (long)(n >> 2);
    split_kernel<<<(unsigned)((n4 + 255) / 256), 256>>>(
        (const float4*)src, (uint2*)h_Ahi, (uint2*)h_Alo, n4);
}
static inline void splitW(const float* src, size_t n)
{
    long n4 = (long)(n >> 2);
    split_kernel<<<(unsigned)((n4 + 255) / 256), 256>>>(
        (const float4*)src, (uint2*)h_Whi, (uint2*)h_Wlo, n4);
}
static inline void gemmT(long wElemOff, const float* bias, const float* res,
                         float* C, int M, int N, int K, int relu, int nz,
                         long sA, long sW, long sB, long sRes, long sC)
{
    dim3 grid(N / 128, M / 128, nz);
    gemm_bf16_kernel<<<grid, 256, GSMEM>>>(
        (const __nv_bfloat16*)h_Ahi, (const __nv_bfloat16*)h_Alo,
        (const __nv_bfloat16*)h_Whi + wElemOff, (const __nv_bfloat16*)h_Wlo + wElemOff,
        bias, res, C, M, N, K, relu, sA, sW, sB, sRes, sC);
}
static inline void gemmS(const float* A, const float* W, const float* bias,
                         const float* res, float* C, int M, int N, int K, int relu)
{
    dim3 grid((N + BN - 1)/BN, (M + BM - 1)/BM);
    gemm_kernel<<<grid, 256>>>(A, W, bias, res, C, M, N, K, relu);
}

extern "C" void kernel_launch(void* const* d_in, const int* in_sizes, int n_in,
                              void* d_out, int out_size)
{
    const float* image      = (const float*)d_in[0];
    const float* text_hidden= (const float*)d_in[1];
    const float* patch_ln_g = (const float*)d_in[2];
    const float* patch_ln_b = (const float*)d_in[3];
    const float* patch_w    = (const float*)d_in[4];
    const float* patch_b    = (const float*)d_in[5];
    const float* text_w     = (const float*)d_in[6];
    const float* text_b     = (const float*)d_in[7];
    const float* attn_in_w  = (const float*)d_in[8];
    const float* attn_in_b  = (const float*)d_in[9];
    const float* attn_out_w = (const float*)d_in[10];
    const float* attn_out_b = (const float*)d_in[11];
    const float* mlp_w1     = (const float*)d_in[12];
    const float* mlp_b1     = (const float*)d_in[13];
    const float* mlp_w2     = (const float*)d_in[14];
    const float* mlp_b2     = (const float*)d_in[15];
    const float* ln_gamma   = (const float*)d_in[16];
    const float* ln_beta    = (const float*)d_in[17];
    const float* fin_g      = (const float*)d_in[18];
    const float* fin_b      = (const float*)d_in[19];
    const float* cls_w1     = (const float*)d_in[20];
    const float* cls_b1     = (const float*)d_in[21];
    const float* cls_w2     = (const float*)d_in[22];
    const float* cls_b2     = (const float*)d_in[23];

    cudaFuncSetAttribute(gemm_bf16_kernel,
                         cudaFuncAttributeMaxDynamicSharedMemorySize, GSMEM);

    float *xp,*tp,*qkvp,*qp,*kvp,*aop,*hidp,*patchp,*featp,*clshp;
    cudaGetSymbolAddress((void**)&xp,    g_x);
    cudaGetSymbolAddress((void**)&tp,    g_t);
    cudaGetSymbolAddress((void**)&qkvp,  g_qkv);
    cudaGetSymbolAddress((void**)&qp,    g_q);
    cudaGetSymbolAddress((void**)&kvp,   g_kv);
    cudaGetSymbolAddress((void**)&aop,   g_ao);
    cudaGetSymbolAddress((void**)&hidp,  g_hid);
    cudaGetSymbolAddress((void**)&patchp,g_patch);
    cudaGetSymbolAddress((void**)&featp, g_feat);
    cudaGetSymbolAddress((void**)&clshp, g_clsh);
    cudaGetSymbolAddress((void**)&h_Ahi, g_bfAhi);
    cudaGetSymbolAddress((void**)&h_Alo, g_bfAlo);
    cudaGetSymbolAddress((void**)&h_Whi, g_bfWhi);
    cudaGetSymbolAddress((void**)&h_Wlo, g_bfWlo);

    float* x1p = xp;
    float* x2p = xp + (size_t)M_*E_;

    const float scale = 0.125f;  // 1/sqrt(64)
    dim3 sc_grid2(13, 13, 2*B_*H_);
    dim3 sc_grid1(13, 13, B_*H_);
    dim3 pv_grid2(7, 2*B_*H_);
    dim3 pv_grid1(7, B_*H_);
    int sm2 = (2*B_*H_*N_*32 + 127) / 128;
    int sm1 = (B_*H_*N_*32 + 127) / 128;

    // --- embedding ---
    patch_ln_kernel<<<M_, 256>>>(image, patch_ln_g, patch_ln_b);
    splitA(patchp, (size_t)M_*PD_);
    splitW(patch_w, (size_t)E_*PD_);
    gemmT(0, patch_b, nullptr, x1p, M_, E_, PD_, 0, 1, 0,0,0,0,0);
    splitA(text_hidden, (size_t)M_*768);
    splitW(text_w, (size_t)E_*768);
    gemmT(0, text_b, nullptr, x2p, M_, E_, 768, 0, 1, 0,0,0,0,0);
    posadd_kernel<<<(2*M_*E_ + 255)/256, 256>>>();

    for (int l = 0; l < L_; l++) {
        const float* g0 = ln_gamma + (size_t)(l*2+0)*E_;
        const float* b0 = ln_beta  + (size_t)(l*2+0)*E_;
        const float* g1 = ln_gamma + (size_t)(l*2+1)*E_;
        const float* b1 = ln_beta  + (size_t)(l*2+1)*E_;

        // --- self-attention, both streams batched (z = stream) ---
        {
            const float* wi = attn_in_w  + (size_t)(l*3)*1536*E_;
            const float* bi = attn_in_b  + (size_t)(l*3)*1536;
            const float* wo = attn_out_w + (size_t)(l*3)*E_*E_;
            const float* bo = attn_out_b + (size_t)(l*3)*E_;
            ln_kernel<<<2*M_, 256>>>(xp, g0, b0, tp);
            splitA(tp, (size_t)2*M_*E_);
            splitW(wi, (size_t)2*1536*E_);
            gemmT(0, bi, nullptr, qkvp, M_, 1536, E_, 0, 2,
                  (long)M_*E_, (long)1536*E_, 1536, 0, (long)M_*1536);
            scores_kernel<<<sc_grid2, 256>>>(qkvp, qkvp + E_, 1536, 1536,
                                             (long)M_*1536, (long)M_*1536, scale);
            softmax_kernel<<<sm2, 128>>>(2*B_*H_*N_);
            pv_kernel<<<pv_grid2, 256>>>(qkvp + 2*E_, 1536,
                                         (long)M_*1536, (long)M_*E_, aop);
            splitA(aop, (size_t)2*M_*E_);
            splitW(wo, (size_t)2*E_*E_);
            gemmT(0, bo, xp, xp, M_, E_, E_, 0, 2,
                  (long)M_*E_, (long)E_*E_, E_, (long)M_*E_, (long)M_*E_);
        }

        // --- guide attention: q from x2, kv from x1, overwrites x1 ---
        {
            const float* wi = attn_in_w  + (size_t)(l*3+2)*1536*E_;
            const float* bi = attn_in_b  + (size_t)(l*3+2)*1536;
            const float* wo = attn_out_w + (size_t)(l*3+2)*E_*E_;
            const float* bo = attn_out_b + (size_t)(l*3+2)*E_;
            splitW(wi, (size_t)1536*E_);              // rows 0..511 = Q, 512..1535 = KV
            splitA(x2p, (size_t)M_*E_);
            gemmT(0, bi, nullptr, qp, M_, E_, E_, 0, 1, 0,0,0,0,0);
            splitA(x1p, (size_t)M_*E_);
            gemmT((long)E_*E_, bi + E_, nullptr, kvp, M_, 2*E_, E_, 0, 1, 0,0,0,0,0);
            scores_kernel<<<sc_grid1, 256>>>(qp, kvp, E_, 2*E_, 0, 0, scale);
            softmax_kernel<<<sm1, 128>>>(B_*H_*N_);
            pv_kernel<<<pv_grid1, 256>>>(kvp + E_, 2*E_, 0, 0, aop);
            splitA(aop, (size_t)M_*E_);
            splitW(wo, (size_t)E_*E_);
            gemmT(0, bo, nullptr, x1p, M_, E_, E_, 0, 1, 0,0,0,0,0);
        }

        // --- MLP, both streams in one M=12544 GEMM (shared weights) ---
        {
            const float* w1  = mlp_w1 + (size_t)l*4*E_*E_;
            const float* bb1 = mlp_b1 + (size_t)l*4*E_;
            const float* w2  = mlp_w2 + (size_t)l*E_*4*E_;
            const float* bb2 = mlp_b2 + (size_t)l*E_;
            ln_kernel<<<2*M_, 256>>>(xp, g1, b1, tp);
            splitA(tp, (size_t)2*M_*E_);
            splitW(w1, (size_t)4*E_*E_);
            gemmT(0, bb1, nullptr, hidp, 2*M_, 4*E_, E_, 1, 1, 0,0,0,0,0);
            splitA(hidp, (size_t)2*M_*4*E_);
            splitW(w2, (size_t)E_*4*E_);
            gemmT(0, bb2, xp, xp, 2*M_, E_, 4*E_, 0, 1, 0,0,0,0,0);
        }
    }

    // --- head (tiny; SIMT path) ---
    final_feat_kernel<<<64, 256>>>(fin_g, fin_b);
    gemmS(featp, cls_w1, cls_b1, nullptr, clshp, B_, 4*E_, 2*E_, 1);
    gemmS(clshp, cls_w2, cls_b2, nullptr, (float*)d_out, B_, NCLS_, 4*E_, 0);
}